// round 1
// baseline (speedup 1.0000x reference)
#include <cuda_runtime.h>

// Problem constants
#define TOK   4096          // B*N = 2*2048
#define SEQ   2048
#define EMB   1024
#define E3    3072
#define NH    16
#define HD    64

// Scratch (device globals: cudaMalloc is forbidden)
__device__ float g_qkv[(size_t)TOK * E3];   // [B,N,3E]
__device__ float g_att[(size_t)TOK * EMB];  // [B,N,E] attention output

// ---------------------------------------------------------------------------
// GEMM: C[M,Nn] = A[M,K] @ Bw[Nn,K]^T + bias[Nn]   (all row-major, fp32)
// BM=BN=128, BK=16, 256 threads, 8x8 per thread, warp z-mapping.
// ---------------------------------------------------------------------------
__global__ __launch_bounds__(256) void gemm_bias(
    const float* __restrict__ A, const float* __restrict__ Bw,
    const float* __restrict__ bias, float* __restrict__ C,
    int M, int Nn, int K)
{
    __shared__ float As[16][132];   // [k][m], padded to 132 (16B-aligned rows)
    __shared__ float Bs[16][132];   // [k][n]

    const int tid  = threadIdx.x;
    const int warp = tid >> 5;
    const int lane = tid & 31;
    // warps 4x2, lanes 4x8 -> conflict-light smem reads
    const int tr = (warp & 3) * 32 + (lane >> 3) * 8;   // row in tile
    const int tc = (warp >> 2) * 64 + (lane & 7) * 8;   // col in tile

    const size_t rowBase = (size_t)blockIdx.y * 128;
    const size_t colBase = (size_t)blockIdx.x * 128;

    const float* Ap = A  + rowBase * K;
    const float* Bp = Bw + colBase * K;

    float acc[8][8];
    #pragma unroll
    for (int i = 0; i < 8; i++)
        #pragma unroll
        for (int j = 0; j < 8; j++) acc[i][j] = 0.f;

    for (int k0 = 0; k0 < K; k0 += 16) {
        // load 128x16 tiles of A and B (512 float4 each; 2 per thread each)
        #pragma unroll
        for (int v = tid; v < 512; v += 256) {
            const int r  = v >> 2;
            const int k4 = (v & 3) << 2;
            float4 a = *(const float4*)(Ap + (size_t)r * K + k0 + k4);
            As[k4 + 0][r] = a.x; As[k4 + 1][r] = a.y;
            As[k4 + 2][r] = a.z; As[k4 + 3][r] = a.w;
            float4 b = *(const float4*)(Bp + (size_t)r * K + k0 + k4);
            Bs[k4 + 0][r] = b.x; Bs[k4 + 1][r] = b.y;
            Bs[k4 + 2][r] = b.z; Bs[k4 + 3][r] = b.w;
        }
        __syncthreads();

        #pragma unroll
        for (int kk = 0; kk < 16; kk++) {
            float ar[8], br[8];
            *(float4*)(ar)     = *(const float4*)&As[kk][tr];
            *(float4*)(ar + 4) = *(const float4*)&As[kk][tr + 4];
            *(float4*)(br)     = *(const float4*)&Bs[kk][tc];
            *(float4*)(br + 4) = *(const float4*)&Bs[kk][tc + 4];
            #pragma unroll
            for (int i = 0; i < 8; i++)
                #pragma unroll
                for (int j = 0; j < 8; j++)
                    acc[i][j] += ar[i] * br[j];
        }
        __syncthreads();
    }

    #pragma unroll
    for (int i = 0; i < 8; i++) {
        const size_t gr = rowBase + tr + i;
        #pragma unroll
        for (int j = 0; j < 8; j += 4) {
            const size_t gc = colBase + tc + j;
            float4 o;
            o.x = acc[i][j + 0] + bias[gc + 0];
            o.y = acc[i][j + 1] + bias[gc + 1];
            o.z = acc[i][j + 2] + bias[gc + 2];
            o.w = acc[i][j + 3] + bias[gc + 3];
            *(float4*)&C[gr * Nn + gc] = o;
        }
    }
}

// ---------------------------------------------------------------------------
// Flash attention, fp32, online softmax.
// grid = (SEQ/64, B*NH), block = 128 threads.
// Thread t: q4 = t&3 (column quarter), rp = t>>2 -> rows {rp, rp+32}.
// smem stride 68 floats per 64-float row -> conflict-free strided access.
// ---------------------------------------------------------------------------
#define AST 68
#define ATTN_SMEM (4 * 64 * AST * 4)   // Qs,Ks,Vs,Ps = 69632 bytes

extern __shared__ float sm_attn[];

__global__ __launch_bounds__(128) void attn_kernel(
    const float* __restrict__ qkv, float* __restrict__ out)
{
    float* Qs = sm_attn;
    float* Ks = sm_attn + 64 * AST;
    float* Vs = sm_attn + 2 * 64 * AST;
    float* Ps = sm_attn + 3 * 64 * AST;

    const int tid = threadIdx.x;
    const int q4  = tid & 3;
    const int rp  = tid >> 2;          // 0..31

    const int qtile = blockIdx.x;      // 0..31
    const int bh    = blockIdx.y;      // 0..31
    const int b     = bh >> 4;
    const int h     = bh & 15;

    const size_t rstride = E3;
    const float* base = qkv + (size_t)b * SEQ * rstride;
    const int qoff = h * HD;
    const int koff = EMB + h * HD;
    const int voff = 2 * EMB + h * HD;
    const float scale = 0.125f;        // 1/sqrt(64)

    // Load Q tile, pre-scaled (1024 float4, 8 per thread)
    for (int v = tid; v < 1024; v += 128) {
        const int r  = v >> 4;
        const int d4 = (v & 15) << 2;
        float4 x = *(const float4*)(base + (size_t)(qtile * 64 + r) * rstride + qoff + d4);
        float* dst = &Qs[r * AST + d4];
        dst[0] = x.x * scale; dst[1] = x.y * scale;
        dst[2] = x.z * scale; dst[3] = x.w * scale;
    }

    float m0 = -1e30f, m1 = -1e30f, l0 = 0.f, l1 = 0.f;
    float o0[16], o1[16];
    #pragma unroll
    for (int i = 0; i < 16; i++) { o0[i] = 0.f; o1[i] = 0.f; }

    for (int kt = 0; kt < SEQ / 64; kt++) {
        // Load K, V tiles
        for (int v = tid; v < 1024; v += 128) {
            const int r  = v >> 4;
            const int d4 = (v & 15) << 2;
            const size_t row = (size_t)(kt * 64 + r) * rstride;
            *(float4*)&Ks[r * AST + d4] = *(const float4*)(base + row + koff + d4);
            *(float4*)&Vs[r * AST + d4] = *(const float4*)(base + row + voff + d4);
        }
        __syncthreads();

        // S = Q K^T (thread: rows rp, rp+32; cols {4i+q4})
        float s0[16], s1[16];
        #pragma unroll
        for (int i = 0; i < 16; i++) { s0[i] = 0.f; s1[i] = 0.f; }

        const float* q0p = &Qs[rp * AST];
        const float* q1p = &Qs[(rp + 32) * AST];
        #pragma unroll 4
        for (int d4 = 0; d4 < 64; d4 += 4) {
            const float4 qa = *(const float4*)(q0p + d4);
            const float4 qb = *(const float4*)(q1p + d4);
            #pragma unroll
            for (int i = 0; i < 16; i++) {
                const int c = 4 * i + q4;
                const float4 kk = *(const float4*)&Ks[c * AST + d4];
                s0[i] += qa.x * kk.x + qa.y * kk.y + qa.z * kk.z + qa.w * kk.w;
                s1[i] += qb.x * kk.x + qb.y * kk.y + qb.z * kk.z + qb.w * kk.w;
            }
        }

        // Online softmax (row shared by 4 consecutive lanes)
        float tm0 = -1e30f, tm1 = -1e30f;
        #pragma unroll
        for (int i = 0; i < 16; i++) { tm0 = fmaxf(tm0, s0[i]); tm1 = fmaxf(tm1, s1[i]); }
        tm0 = fmaxf(tm0, __shfl_xor_sync(0xFFFFFFFFu, tm0, 1));
        tm0 = fmaxf(tm0, __shfl_xor_sync(0xFFFFFFFFu, tm0, 2));
        tm1 = fmaxf(tm1, __shfl_xor_sync(0xFFFFFFFFu, tm1, 1));
        tm1 = fmaxf(tm1, __shfl_xor_sync(0xFFFFFFFFu, tm1, 2));

        const float nm0 = fmaxf(m0, tm0);
        const float nm1 = fmaxf(m1, tm1);

        float ts0 = 0.f, ts1 = 0.f;
        #pragma unroll
        for (int i = 0; i < 16; i++) {
            s0[i] = __expf(s0[i] - nm0); ts0 += s0[i];
            s1[i] = __expf(s1[i] - nm1); ts1 += s1[i];
        }
        ts0 += __shfl_xor_sync(0xFFFFFFFFu, ts0, 1);
        ts0 += __shfl_xor_sync(0xFFFFFFFFu, ts0, 2);
        ts1 += __shfl_xor_sync(0xFFFFFFFFu, ts1, 1);
        ts1 += __shfl_xor_sync(0xFFFFFFFFu, ts1, 2);

        const float a0 = __expf(m0 - nm0);
        const float a1 = __expf(m1 - nm1);
        l0 = l0 * a0 + ts0;  l1 = l1 * a1 + ts1;
        m0 = nm0;            m1 = nm1;
        #pragma unroll
        for (int i = 0; i < 16; i++) { o0[i] *= a0; o1[i] *= a1; }

        // Write P (same-warp producer/consumer -> syncwarp is enough)
        #pragma unroll
        for (int i = 0; i < 16; i++) {
            const int c = 4 * i + q4;
            Ps[rp * AST + c]        = s0[i];
            Ps[(rp + 32) * AST + c] = s1[i];
        }
        __syncwarp();

        // O += P V  (thread owns float4 granules g = dd*4 + q4 of the d axis)
        #pragma unroll 8
        for (int j = 0; j < 64; j++) {
            const float p0 = Ps[rp * AST + j];
            const float p1 = Ps[(rp + 32) * AST + j];
            #pragma unroll
            for (int dd = 0; dd < 4; dd++) {
                const float4 vv = *(const float4*)&Vs[j * AST + (dd * 4 + q4) * 4];
                o0[dd * 4 + 0] += p0 * vv.x;  o1[dd * 4 + 0] += p1 * vv.x;
                o0[dd * 4 + 1] += p0 * vv.y;  o1[dd * 4 + 1] += p1 * vv.y;
                o0[dd * 4 + 2] += p0 * vv.z;  o1[dd * 4 + 2] += p1 * vv.z;
                o0[dd * 4 + 3] += p0 * vv.w;  o1[dd * 4 + 3] += p1 * vv.w;
            }
        }
        __syncthreads();   // protect Ks/Vs/Ps before next tile's loads
    }

    // Epilogue: normalize and store to [b, n, h*64 + d]
    const float inv0 = 1.f / l0;
    const float inv1 = 1.f / l1;
    const int row0 = qtile * 64 + rp;
    float* op0 = out + ((size_t)(b * SEQ + row0)) * EMB + h * HD;
    float* op1 = out + ((size_t)(b * SEQ + row0 + 32)) * EMB + h * HD;
    #pragma unroll
    for (int dd = 0; dd < 4; dd++) {
        const int g = (dd * 4 + q4) * 4;
        float4 w0, w1;
        w0.x = o0[dd * 4 + 0] * inv0; w0.y = o0[dd * 4 + 1] * inv0;
        w0.z = o0[dd * 4 + 2] * inv0; w0.w = o0[dd * 4 + 3] * inv0;
        w1.x = o1[dd * 4 + 0] * inv1; w1.y = o1[dd * 4 + 1] * inv1;
        w1.z = o1[dd * 4 + 2] * inv1; w1.w = o1[dd * 4 + 3] * inv1;
        *(float4*)&op0[g] = w0;
        *(float4*)&op1[g] = w1;
    }
}

// ---------------------------------------------------------------------------
extern "C" void kernel_launch(void* const* d_in, const int* in_sizes, int n_in,
                              void* d_out, int out_size)
{
    const float* x     = (const float*)d_in[0];
    const float* w_in  = (const float*)d_in[1];
    const float* b_in  = (const float*)d_in[2];
    const float* w_out = (const float*)d_in[3];
    const float* b_out = (const float*)d_in[4];
    float* out = (float*)d_out;

    float *qkv, *att;
    cudaGetSymbolAddress((void**)&qkv, g_qkv);
    cudaGetSymbolAddress((void**)&att, g_att);

    cudaFuncSetAttribute(attn_kernel,
                         cudaFuncAttributeMaxDynamicSharedMemorySize, ATTN_SMEM);

    // 1) QKV projection: [4096,3072] = x[4096,1024] @ w_in^T + b_in
    gemm_bias<<<dim3(E3 / 128, TOK / 128), 256>>>(x, w_in, b_in, qkv,
                                                  TOK, E3, EMB);
    // 2) Multi-head flash attention
    attn_kernel<<<dim3(SEQ / 64, 2 * NH), 128, ATTN_SMEM>>>(qkv, att);

    // 3) Output projection: [4096,1024] = att @ w_out^T + b_out
    gemm_bias<<<dim3(EMB / 128, TOK / 128), 256>>>(att, w_out, b_out, out,
                                                   TOK, EMB, EMB);
}

// round 3
// speedup vs baseline: 1.4220x; 1.4220x over previous
#include <cuda_runtime.h>
#include <cuda_bf16.h>
#include <cstdint>

#define TOK 4096
#define SEQ 2048
#define EMB 1024
#define E3  3072
#define NH  16
#define HD  64

// ---------------- scratch (cudaMalloc forbidden) ----------------
__device__ float g_qkv[(size_t)TOK * E3];
__device__ float g_att[(size_t)TOK * EMB];
__device__ __nv_bfloat16 g_xh[(size_t)TOK * EMB],  g_xl[(size_t)TOK * EMB];
__device__ __nv_bfloat16 g_wih[(size_t)E3 * EMB],  g_wil[(size_t)E3 * EMB];
__device__ __nv_bfloat16 g_woh[(size_t)EMB * EMB], g_wol[(size_t)EMB * EMB];
__device__ __nv_bfloat16 g_ah[(size_t)TOK * EMB],  g_al[(size_t)TOK * EMB];

// ---------------- helpers ----------------
__device__ __forceinline__ uint32_t smem_u32(const void* p) {
    uint32_t a;
    asm("{ .reg .u64 t; cvta.to.shared.u64 t, %1; cvt.u32.u64 %0, t; }"
        : "=r"(a) : "l"(p));
    return a;
}
__device__ __forceinline__ void cp_async16(uint32_t dst, const void* src) {
    asm volatile("cp.async.cg.shared.global [%0], [%1], 16;"
                 :: "r"(dst), "l"(src));
}
#define CP_COMMIT()  asm volatile("cp.async.commit_group;" ::: "memory")
#define CP_WAIT(n)   asm volatile("cp.async.wait_group %0;" :: "n"(n) : "memory")

#define LDSM4(r, a)                                                         \
    asm volatile("ldmatrix.sync.aligned.m8n8.x4.shared.b16 "                \
                 "{%0,%1,%2,%3}, [%4];"                                     \
                 : "=r"((r)[0]), "=r"((r)[1]), "=r"((r)[2]), "=r"((r)[3])   \
                 : "r"(a))

__device__ __forceinline__ void mma16816(float* d, const uint32_t* a,
                                         const uint32_t* b) {
    asm volatile(
        "mma.sync.aligned.m16n8k16.row.col.f32.bf16.bf16.f32 "
        "{%0,%1,%2,%3}, {%4,%5,%6,%7}, {%8,%9}, {%0,%1,%2,%3};"
        : "+f"(d[0]), "+f"(d[1]), "+f"(d[2]), "+f"(d[3])
        : "r"(a[0]), "r"(a[1]), "r"(a[2]), "r"(a[3]), "r"(b[0]), "r"(b[1]));
}

// ---------------- fp32 -> bf16 hi/lo split ----------------
__global__ __launch_bounds__(256) void split_bf16(
    const float* __restrict__ s, __nv_bfloat16* __restrict__ h,
    __nv_bfloat16* __restrict__ l, int n4)
{
    int i = blockIdx.x * blockDim.x + threadIdx.x;
    if (i >= n4) return;
    float4 v = ((const float4*)s)[i];
    __nv_bfloat16 h0 = __float2bfloat16(v.x);
    __nv_bfloat16 h1 = __float2bfloat16(v.y);
    __nv_bfloat16 h2 = __float2bfloat16(v.z);
    __nv_bfloat16 h3 = __float2bfloat16(v.w);
    __nv_bfloat16 l0 = __float2bfloat16(v.x - __bfloat162float(h0));
    __nv_bfloat16 l1 = __float2bfloat16(v.y - __bfloat162float(h1));
    __nv_bfloat16 l2 = __float2bfloat16(v.z - __bfloat162float(h2));
    __nv_bfloat16 l3 = __float2bfloat16(v.w - __bfloat162float(h3));
    __nv_bfloat162* hp = (__nv_bfloat162*)h;
    __nv_bfloat162* lp = (__nv_bfloat162*)l;
    hp[2 * i]     = __nv_bfloat162(h0, h1);
    hp[2 * i + 1] = __nv_bfloat162(h2, h3);
    lp[2 * i]     = __nv_bfloat162(l0, l1);
    lp[2 * i + 1] = __nv_bfloat162(l2, l3);
}

// ---------------- split-bf16 GEMM on mma.sync (HMMA) ----------------
// C[M,N] = (Ah+Al)[M,K] @ (Bh+Bl)[N,K]^T + bias, fp32 out.
// 128x128 CTA tile, 8 warps (2x4), warp tile 64x32, KC=64, double-buffered.
#define KC     64
#define ROWB   144                  // 72 bf16 per smem row (pad 64+8)
#define TILE_B (128 * ROWB)         // 18432 B per operand tile
#define STAGE_B (4 * TILE_B)        // Ah, Al, Bh, Bl
#define GEMM_SMEM (2 * STAGE_B)     // 147456 B

__global__ __launch_bounds__(256, 1) void mma_gemm(
    const __nv_bfloat16* __restrict__ Ah, const __nv_bfloat16* __restrict__ Al,
    const __nv_bfloat16* __restrict__ Bh, const __nv_bfloat16* __restrict__ Bl,
    const float* __restrict__ bias, float* __restrict__ C, int Nn, int K)
{
    extern __shared__ char smem[];
    const uint32_t sb = smem_u32(smem);
    const int tid  = threadIdx.x;
    const int wid  = tid >> 5;
    const int lane = tid & 31;
    const int wm = wid >> 2;        // 0..1  (M direction, 64 rows)
    const int wn = wid & 3;         // 0..3  (N direction, 32 cols)

    const size_t rowBase = (size_t)blockIdx.y * 128;
    const size_t colBase = (size_t)blockIdx.x * 128;

    const __nv_bfloat16* src0 = Ah + rowBase * K;
    const __nv_bfloat16* src1 = Al + rowBase * K;
    const __nv_bfloat16* src2 = Bh + colBase * K;
    const __nv_bfloat16* src3 = Bl + colBase * K;

    // chunk loader: 4 tiles x 128 rows x 8 x 16B
    const int lr = tid >> 3;        // 0..31 row group
    const int lj = tid & 7;         // 16B chunk in row
    auto load_chunk = [&](int c, int stage) {
        const uint32_t st = sb + stage * STAGE_B;
        #pragma unroll
        for (int it = 0; it < 16; it++) {
            const int t = it >> 2;              // tile 0..3 (compile-time)
            const int r = lr + (it & 3) * 32;   // row 0..127
            const uint32_t dst = st + t * TILE_B + r * ROWB + lj * 16;
            const __nv_bfloat16* gsrc =
                (t == 0 ? src0 : t == 1 ? src1 : t == 2 ? src2 : src3);
            cp_async16(dst, gsrc + (size_t)r * K + c * KC + lj * 8);
        }
        CP_COMMIT();
    };

    float acc[4][4][4];
    #pragma unroll
    for (int i = 0; i < 4; i++)
        #pragma unroll
        for (int j = 0; j < 4; j++)
            #pragma unroll
            for (int k = 0; k < 4; k++) acc[i][j][k] = 0.f;

    // ldmatrix per-lane address components
    const int arow  = ((lane >> 3) & 1) * 8 + (lane & 7);  // A: row in m16 tile
    const int acol  = ((lane >> 4) & 1) * 8;               // A: k8 block
    const int brow  = ((lane >> 4) & 1) * 8 + (lane & 7);  // B: row in n16 pair
    const int bcol  = ((lane >> 3) & 1) * 8;               // B: k8 block

    const int nch = K / KC;
    load_chunk(0, 0);

    for (int c = 0; c < nch; c++) {
        const int s = c & 1;
        if (c + 1 < nch) { load_chunk(c + 1, s ^ 1); CP_WAIT(1); }
        else             { CP_WAIT(0); }
        __syncthreads();

        const uint32_t stA = sb + s * STAGE_B;
        const uint32_t stB = stA + 2 * TILE_B;

        #pragma unroll
        for (int kk = 0; kk < 4; kk++) {
            const int k0 = kk * 16;
            uint32_t ah[4][4], al[4][4], bh[4][2], bl[4][2];
            #pragma unroll
            for (int mt = 0; mt < 4; mt++) {
                const uint32_t ra = stA + (wm * 64 + mt * 16 + arow) * ROWB
                                        + (k0 + acol) * 2;
                LDSM4(ah[mt], ra);
                LDSM4(al[mt], ra + TILE_B);
            }
            #pragma unroll
            for (int np = 0; np < 2; np++) {
                const uint32_t rb = stB + (wn * 32 + np * 16 + brow) * ROWB
                                        + (k0 + bcol) * 2;
                uint32_t r[4];
                LDSM4(r, rb);
                bh[2 * np][0]     = r[0]; bh[2 * np][1]     = r[1];
                bh[2 * np + 1][0] = r[2]; bh[2 * np + 1][1] = r[3];
                LDSM4(r, rb + TILE_B);
                bl[2 * np][0]     = r[0]; bl[2 * np][1]     = r[1];
                bl[2 * np + 1][0] = r[2]; bl[2 * np + 1][1] = r[3];
            }
            #pragma unroll
            for (int mt = 0; mt < 4; mt++)
                #pragma unroll
                for (int nt = 0; nt < 4; nt++) {
                    mma16816(acc[mt][nt], ah[mt], bh[nt]);
                    mma16816(acc[mt][nt], ah[mt], bl[nt]);
                    mma16816(acc[mt][nt], al[mt], bh[nt]);
                }
        }
        __syncthreads();
    }

    // epilogue: registers -> C with bias
    const int g  = lane >> 2;
    const int t4 = lane & 3;
    #pragma unroll
    for (int mt = 0; mt < 4; mt++) {
        const size_t r0 = rowBase + wm * 64 + mt * 16 + g;
        #pragma unroll
        for (int nt = 0; nt < 4; nt++) {
            const size_t cc = colBase + wn * 32 + nt * 8 + t4 * 2;
            const float b0 = bias[cc], b1 = bias[cc + 1];
            float2 v0, v1;
            v0.x = acc[mt][nt][0] + b0; v0.y = acc[mt][nt][1] + b1;
            v1.x = acc[mt][nt][2] + b0; v1.y = acc[mt][nt][3] + b1;
            *(float2*)&C[r0 * Nn + cc]       = v0;
            *(float2*)&C[(r0 + 8) * Nn + cc] = v1;
        }
    }
}

// ---------------------------------------------------------------------------
// Flash attention, fp32, online softmax (unchanged from round 1).
// ---------------------------------------------------------------------------
#define AST 68
#define ATTN_SMEM (4 * 64 * AST * 4)

extern __shared__ float sm_attn[];

__global__ __launch_bounds__(128) void attn_kernel(
    const float* __restrict__ qkv, float* __restrict__ out)
{
    float* Qs = sm_attn;
    float* Ks = sm_attn + 64 * AST;
    float* Vs = sm_attn + 2 * 64 * AST;
    float* Ps = sm_attn + 3 * 64 * AST;

    const int tid = threadIdx.x;
    const int q4  = tid & 3;
    const int rp  = tid >> 2;

    const int qtile = blockIdx.x;
    const int bh    = blockIdx.y;
    const int b     = bh >> 4;
    const int h     = bh & 15;

    const size_t rstride = E3;
    const float* base = qkv + (size_t)b * SEQ * rstride;
    const int qoff = h * HD;
    const int koff = EMB + h * HD;
    const int voff = 2 * EMB + h * HD;
    const float scale = 0.125f;

    for (int v = tid; v < 1024; v += 128) {
        const int r  = v >> 4;
        const int d4 = (v & 15) << 2;
        float4 x = *(const float4*)(base + (size_t)(qtile * 64 + r) * rstride + qoff + d4);
        float* dst = &Qs[r * AST + d4];
        dst[0] = x.x * scale; dst[1] = x.y * scale;
        dst[2] = x.z * scale; dst[3] = x.w * scale;
    }

    float m0 = -1e30f, m1 = -1e30f, l0 = 0.f, l1 = 0.f;
    float o0[16], o1[16];
    #pragma unroll
    for (int i = 0; i < 16; i++) { o0[i] = 0.f; o1[i] = 0.f; }

    for (int kt = 0; kt < SEQ / 64; kt++) {
        for (int v = tid; v < 1024; v += 128) {
            const int r  = v >> 4;
            const int d4 = (v & 15) << 2;
            const size_t row = (size_t)(kt * 64 + r) * rstride;
            *(float4*)&Ks[r * AST + d4] = *(const float4*)(base + row + koff + d4);
            *(float4*)&Vs[r * AST + d4] = *(const float4*)(base + row + voff + d4);
        }
        __syncthreads();

        float s0[16], s1[16];
        #pragma unroll
        for (int i = 0; i < 16; i++) { s0[i] = 0.f; s1[i] = 0.f; }

        const float* q0p = &Qs[rp * AST];
        const float* q1p = &Qs[(rp + 32) * AST];
        #pragma unroll 4
        for (int d4 = 0; d4 < 64; d4 += 4) {
            const float4 qa = *(const float4*)(q0p + d4);
            const float4 qb = *(const float4*)(q1p + d4);
            #pragma unroll
            for (int i = 0; i < 16; i++) {
                const int cix = 4 * i + q4;
                const float4 kk = *(const float4*)&Ks[cix * AST + d4];
                s0[i] += qa.x * kk.x + qa.y * kk.y + qa.z * kk.z + qa.w * kk.w;
                s1[i] += qb.x * kk.x + qb.y * kk.y + qb.z * kk.z + qb.w * kk.w;
            }
        }

        float tm0 = -1e30f, tm1 = -1e30f;
        #pragma unroll
        for (int i = 0; i < 16; i++) { tm0 = fmaxf(tm0, s0[i]); tm1 = fmaxf(tm1, s1[i]); }
        tm0 = fmaxf(tm0, __shfl_xor_sync(0xFFFFFFFFu, tm0, 1));
        tm0 = fmaxf(tm0, __shfl_xor_sync(0xFFFFFFFFu, tm0, 2));
        tm1 = fmaxf(tm1, __shfl_xor_sync(0xFFFFFFFFu, tm1, 1));
        tm1 = fmaxf(tm1, __shfl_xor_sync(0xFFFFFFFFu, tm1, 2));

        const float nm0 = fmaxf(m0, tm0);
        const float nm1 = fmaxf(m1, tm1);

        float ts0 = 0.f, ts1 = 0.f;
        #pragma unroll
        for (int i = 0; i < 16; i++) {
            s0[i] = __expf(s0[i] - nm0); ts0 += s0[i];
            s1[i] = __expf(s1[i] - nm1); ts1 += s1[i];
        }
        ts0 += __shfl_xor_sync(0xFFFFFFFFu, ts0, 1);
        ts0 += __shfl_xor_sync(0xFFFFFFFFu, ts0, 2);
        ts1 += __shfl_xor_sync(0xFFFFFFFFu, ts1, 1);
        ts1 += __shfl_xor_sync(0xFFFFFFFFu, ts1, 2);

        const float a0 = __expf(m0 - nm0);
        const float a1 = __expf(m1 - nm1);
        l0 = l0 * a0 + ts0;  l1 = l1 * a1 + ts1;
        m0 = nm0;            m1 = nm1;
        #pragma unroll
        for (int i = 0; i < 16; i++) { o0[i] *= a0; o1[i] *= a1; }

        #pragma unroll
        for (int i = 0; i < 16; i++) {
            const int cix = 4 * i + q4;
            Ps[rp * AST + cix]        = s0[i];
            Ps[(rp + 32) * AST + cix] = s1[i];
        }
        __syncwarp();

        #pragma unroll 8
        for (int j = 0; j < 64; j++) {
            const float p0 = Ps[rp * AST + j];
            const float p1 = Ps[(rp + 32) * AST + j];
            #pragma unroll
            for (int dd = 0; dd < 4; dd++) {
                const float4 vv = *(const float4*)&Vs[j * AST + (dd * 4 + q4) * 4];
                o0[dd * 4 + 0] += p0 * vv.x;  o1[dd * 4 + 0] += p1 * vv.x;
                o0[dd * 4 + 1] += p0 * vv.y;  o1[dd * 4 + 1] += p1 * vv.y;
                o0[dd * 4 + 2] += p0 * vv.z;  o1[dd * 4 + 2] += p1 * vv.z;
                o0[dd * 4 + 3] += p0 * vv.w;  o1[dd * 4 + 3] += p1 * vv.w;
            }
        }
        __syncthreads();
    }

    const float inv0 = 1.f / l0;
    const float inv1 = 1.f / l1;
    const int row0 = qtile * 64 + rp;
    float* op0 = out + ((size_t)(b * SEQ + row0)) * EMB + h * HD;
    float* op1 = out + ((size_t)(b * SEQ + row0 + 32)) * EMB + h * HD;
    #pragma unroll
    for (int dd = 0; dd < 4; dd++) {
        const int g = (dd * 4 + q4) * 4;
        float4 w0, w1;
        w0.x = o0[dd * 4 + 0] * inv0; w0.y = o0[dd * 4 + 1] * inv0;
        w0.z = o0[dd * 4 + 2] * inv0; w0.w = o0[dd * 4 + 3] * inv0;
        w1.x = o1[dd * 4 + 0] * inv1; w1.y = o1[dd * 4 + 1] * inv1;
        w1.z = o1[dd * 4 + 2] * inv1; w1.w = o1[dd * 4 + 3] * inv1;
        *(float4*)&op0[g] = w0;
        *(float4*)&op1[g] = w1;
    }
}

// ---------------------------------------------------------------------------
extern "C" void kernel_launch(void* const* d_in, const int* in_sizes, int n_in,
                              void* d_out, int out_size)
{
    const float* x     = (const float*)d_in[0];
    const float* w_in  = (const float*)d_in[1];
    const float* b_in  = (const float*)d_in[2];
    const float* w_out = (const float*)d_in[3];
    const float* b_out = (const float*)d_in[4];
    float* out = (float*)d_out;

    float *qkv, *att;
    __nv_bfloat16 *xh, *xl, *wih, *wil, *woh, *wol, *ah, *al;
    cudaGetSymbolAddress((void**)&qkv, g_qkv);
    cudaGetSymbolAddress((void**)&att, g_att);
    cudaGetSymbolAddress((void**)&xh,  g_xh);
    cudaGetSymbolAddress((void**)&xl,  g_xl);
    cudaGetSymbolAddress((void**)&wih, g_wih);
    cudaGetSymbolAddress((void**)&wil, g_wil);
    cudaGetSymbolAddress((void**)&woh, g_woh);
    cudaGetSymbolAddress((void**)&wol, g_wol);
    cudaGetSymbolAddress((void**)&ah,  g_ah);
    cudaGetSymbolAddress((void**)&al,  g_al);

    cudaFuncSetAttribute(attn_kernel,
                         cudaFuncAttributeMaxDynamicSharedMemorySize, ATTN_SMEM);
    cudaFuncSetAttribute(mma_gemm,
                         cudaFuncAttributeMaxDynamicSharedMemorySize, GEMM_SMEM);

    // 0) fp32 -> bf16 hi/lo splits
    {
        int n4;
        n4 = TOK * EMB / 4; split_bf16<<<(n4 + 255) / 256, 256>>>(x,     xh,  xl,  n4);
        n4 = E3  * EMB / 4; split_bf16<<<(n4 + 255) / 256, 256>>>(w_in,  wih, wil, n4);
        n4 = EMB * EMB / 4; split_bf16<<<(n4 + 255) / 256, 256>>>(w_out, woh, wol, n4);
    }

    // 1) QKV projection on HMMA: [4096,3072]
    mma_gemm<<<dim3(E3 / 128, TOK / 128), 256, GEMM_SMEM>>>(
        xh, xl, wih, wil, b_in, qkv, E3, EMB);

    // 2) fp32 flash attention
    attn_kernel<<<dim3(SEQ / 64, 2 * NH), 128, ATTN_SMEM>>>(qkv, att);

    // 3) split attention output, then out-projection on HMMA: [4096,1024]
    {
        int n4 = TOK * EMB / 4;
        split_bf16<<<(n4 + 255) / 256, 256>>>(att, ah, al, n4);
    }
    mma_gemm<<<dim3(EMB / 128, TOK / 128), 256, GEMM_SMEM>>>(
        ah, al, woh, wol, b_out, out, EMB, EMB);
}

// round 4
// speedup vs baseline: 3.1577x; 2.2206x over previous
#include <cuda_runtime.h>
#include <cuda_bf16.h>
#include <cstdint>

#define TOK 4096
#define SEQ 2048
#define EMB 1024
#define E3  3072
#define NH  16
#define HD  64

// ---------------- scratch (cudaMalloc forbidden) ----------------
__device__ float g_qkv[(size_t)TOK * E3];
__device__ __nv_bfloat16 g_xh[(size_t)TOK * EMB],  g_xl[(size_t)TOK * EMB];
__device__ __nv_bfloat16 g_wih[(size_t)E3 * EMB],  g_wil[(size_t)E3 * EMB];
__device__ __nv_bfloat16 g_woh[(size_t)EMB * EMB], g_wol[(size_t)EMB * EMB];
__device__ __nv_bfloat16 g_ah[(size_t)TOK * EMB],  g_al[(size_t)TOK * EMB];
// per-(b,h) contiguous q/k/v splits: [B*NH][SEQ][HD]
__device__ __nv_bfloat16 g_qh[(size_t)TOK * EMB], g_ql[(size_t)TOK * EMB];
__device__ __nv_bfloat16 g_kh[(size_t)TOK * EMB], g_kl[(size_t)TOK * EMB];
__device__ __nv_bfloat16 g_vh[(size_t)TOK * EMB], g_vl[(size_t)TOK * EMB];

// ---------------- helpers ----------------
__device__ __forceinline__ uint32_t smem_u32(const void* p) {
    uint32_t a;
    asm("{ .reg .u64 t; cvta.to.shared.u64 t, %1; cvt.u32.u64 %0, t; }"
        : "=r"(a) : "l"(p));
    return a;
}
__device__ __forceinline__ void cp_async16(uint32_t dst, const void* src) {
    asm volatile("cp.async.cg.shared.global [%0], [%1], 16;"
                 :: "r"(dst), "l"(src));
}
#define CP_COMMIT()  asm volatile("cp.async.commit_group;" ::: "memory")
#define CP_WAIT(n)   asm volatile("cp.async.wait_group %0;" :: "n"(n) : "memory")

#define LDSM4(r, a)                                                         \
    asm volatile("ldmatrix.sync.aligned.m8n8.x4.shared.b16 "                \
                 "{%0,%1,%2,%3}, [%4];"                                     \
                 : "=r"((r)[0]), "=r"((r)[1]), "=r"((r)[2]), "=r"((r)[3])   \
                 : "r"(a))
#define LDSM4T(r, a)                                                        \
    asm volatile("ldmatrix.sync.aligned.m8n8.x4.trans.shared.b16 "          \
                 "{%0,%1,%2,%3}, [%4];"                                     \
                 : "=r"((r)[0]), "=r"((r)[1]), "=r"((r)[2]), "=r"((r)[3])   \
                 : "r"(a))

__device__ __forceinline__ void mma16816(float* d, const uint32_t* a,
                                         const uint32_t* b) {
    asm volatile(
        "mma.sync.aligned.m16n8k16.row.col.f32.bf16.bf16.f32 "
        "{%0,%1,%2,%3}, {%4,%5,%6,%7}, {%8,%9}, {%0,%1,%2,%3};"
        : "+f"(d[0]), "+f"(d[1]), "+f"(d[2]), "+f"(d[3])
        : "r"(a[0]), "r"(a[1]), "r"(a[2]), "r"(a[3]), "r"(b[0]), "r"(b[1]));
}
__device__ __forceinline__ float ex2f(float x) {
    float y; asm("ex2.approx.ftz.f32 %0, %1;" : "=f"(y) : "f"(x)); return y;
}
// pack {lo, hi} floats -> bf16x2 (lo in low half)
__device__ __forceinline__ uint32_t pack_bf16x2(float lo, float hi) {
    uint32_t r;
    asm("cvt.rn.bf16x2.f32 %0, %1, %2;" : "=r"(r) : "f"(hi), "f"(lo));
    return r;
}
__device__ __forceinline__ float bf16rt(float x) {
    return __bfloat162float(__float2bfloat16(x));
}

// ---------------- fp32 -> bf16 hi/lo split (generic) ----------------
__global__ __launch_bounds__(256) void split_bf16(
    const float* __restrict__ s, __nv_bfloat16* __restrict__ h,
    __nv_bfloat16* __restrict__ l, int n4)
{
    int i = blockIdx.x * blockDim.x + threadIdx.x;
    if (i >= n4) return;
    float4 v = ((const float4*)s)[i];
    __nv_bfloat16 h0 = __float2bfloat16(v.x);
    __nv_bfloat16 h1 = __float2bfloat16(v.y);
    __nv_bfloat16 h2 = __float2bfloat16(v.z);
    __nv_bfloat16 h3 = __float2bfloat16(v.w);
    __nv_bfloat16 l0 = __float2bfloat16(v.x - __bfloat162float(h0));
    __nv_bfloat16 l1 = __float2bfloat16(v.y - __bfloat162float(h1));
    __nv_bfloat16 l2 = __float2bfloat16(v.z - __bfloat162float(h2));
    __nv_bfloat16 l3 = __float2bfloat16(v.w - __bfloat162float(h3));
    __nv_bfloat162* hp = (__nv_bfloat162*)h;
    __nv_bfloat162* lp = (__nv_bfloat162*)l;
    hp[2 * i]     = __nv_bfloat162(h0, h1);
    hp[2 * i + 1] = __nv_bfloat162(h2, h3);
    lp[2 * i]     = __nv_bfloat162(l0, l1);
    lp[2 * i + 1] = __nv_bfloat162(l2, l3);
}

// ---------------- qkv[TOK][3E] -> per-(b,h) q/k/v hi/lo splits ----------
// q pre-scaled by 0.125 * log2(e) so softmax runs in base-2.
#define QSCALE 0.18033688011112042f
__global__ __launch_bounds__(256) void split_qkv(
    const float* __restrict__ qkv,
    __nv_bfloat16* __restrict__ qh, __nv_bfloat16* __restrict__ ql,
    __nv_bfloat16* __restrict__ kh, __nv_bfloat16* __restrict__ kl,
    __nv_bfloat16* __restrict__ vh, __nv_bfloat16* __restrict__ vl)
{
    int i = blockIdx.x * blockDim.x + threadIdx.x;     // over TOK*3E/4
    if (i >= TOK * E3 / 4) return;
    const int tok = i / (E3 / 4);
    const int col = (i % (E3 / 4)) * 4;
    float4 v = ((const float4*)qkv)[i];

    const int sec = col >> 10;          // 0=q 1=k 2=v
    const int cc  = col & 1023;
    const int h   = cc >> 6;
    const int d   = cc & 63;
    __nv_bfloat16 *ph, *pl;
    if (sec == 0) { ph = qh; pl = ql; v.x *= QSCALE; v.y *= QSCALE;
                    v.z *= QSCALE; v.w *= QSCALE; }
    else if (sec == 1) { ph = kh; pl = kl; }
    else               { ph = vh; pl = vl; }

    const size_t o = (((size_t)((tok >> 11) * NH + h)) * SEQ + (tok & 2047))
                     * HD + d;
    uint32_t h01 = pack_bf16x2(v.x, v.y), h23 = pack_bf16x2(v.z, v.w);
    float fx = bf16rt(v.x), fy = bf16rt(v.y), fz = bf16rt(v.z), fw = bf16rt(v.w);
    uint32_t l01 = pack_bf16x2(v.x - fx, v.y - fy);
    uint32_t l23 = pack_bf16x2(v.z - fz, v.w - fw);
    *(uint32_t*)&ph[o]     = h01;  *(uint32_t*)&ph[o + 2] = h23;
    *(uint32_t*)&pl[o]     = l01;  *(uint32_t*)&pl[o + 2] = l23;
}

// ---------------- split-bf16 GEMM on mma.sync (HMMA) — round-3, validated --
#define KC     64
#define ROWB   144
#define TILE_B (128 * ROWB)
#define STAGE_B (4 * TILE_B)
#define GEMM_SMEM (2 * STAGE_B)

__global__ __launch_bounds__(256, 1) void mma_gemm(
    const __nv_bfloat16* __restrict__ Ah, const __nv_bfloat16* __restrict__ Al,
    const __nv_bfloat16* __restrict__ Bh, const __nv_bfloat16* __restrict__ Bl,
    const float* __restrict__ bias, float* __restrict__ C, int Nn, int K)
{
    extern __shared__ char smem[];
    const uint32_t sb = smem_u32(smem);
    const int tid  = threadIdx.x;
    const int wid  = tid >> 5;
    const int lane = tid & 31;
    const int wm = wid >> 2;
    const int wn = wid & 3;

    const size_t rowBase = (size_t)blockIdx.y * 128;
    const size_t colBase = (size_t)blockIdx.x * 128;

    const __nv_bfloat16* src0 = Ah + rowBase * K;
    const __nv_bfloat16* src1 = Al + rowBase * K;
    const __nv_bfloat16* src2 = Bh + colBase * K;
    const __nv_bfloat16* src3 = Bl + colBase * K;

    const int lr = tid >> 3;
    const int lj = tid & 7;
    auto load_chunk = [&](int c, int stage) {
        const uint32_t st = sb + stage * STAGE_B;
        #pragma unroll
        for (int it = 0; it < 16; it++) {
            const int t = it >> 2;
            const int r = lr + (it & 3) * 32;
            const uint32_t dst = st + t * TILE_B + r * ROWB + lj * 16;
            const __nv_bfloat16* gsrc =
                (t == 0 ? src0 : t == 1 ? src1 : t == 2 ? src2 : src3);
            cp_async16(dst, gsrc + (size_t)r * K + c * KC + lj * 8);
        }
        CP_COMMIT();
    };

    float acc[4][4][4];
    #pragma unroll
    for (int i = 0; i < 4; i++)
        #pragma unroll
        for (int j = 0; j < 4; j++)
            #pragma unroll
            for (int k = 0; k < 4; k++) acc[i][j][k] = 0.f;

    const int arow = ((lane >> 3) & 1) * 8 + (lane & 7);
    const int acol = ((lane >> 4) & 1) * 8;
    const int brow = ((lane >> 4) & 1) * 8 + (lane & 7);
    const int bcol = ((lane >> 3) & 1) * 8;

    const int nch = K / KC;
    load_chunk(0, 0);

    for (int c = 0; c < nch; c++) {
        const int s = c & 1;
        if (c + 1 < nch) { load_chunk(c + 1, s ^ 1); CP_WAIT(1); }
        else             { CP_WAIT(0); }
        __syncthreads();

        const uint32_t stA = sb + s * STAGE_B;
        const uint32_t stB = stA + 2 * TILE_B;

        #pragma unroll
        for (int kk = 0; kk < 4; kk++) {
            const int k0 = kk * 16;
            uint32_t ah[4][4], al[4][4], bh[4][2], bl[4][2];
            #pragma unroll
            for (int mt = 0; mt < 4; mt++) {
                const uint32_t ra = stA + (wm * 64 + mt * 16 + arow) * ROWB
                                        + (k0 + acol) * 2;
                LDSM4(ah[mt], ra);
                LDSM4(al[mt], ra + TILE_B);
            }
            #pragma unroll
            for (int np = 0; np < 2; np++) {
                const uint32_t rb = stB + (wn * 32 + np * 16 + brow) * ROWB
                                        + (k0 + bcol) * 2;
                uint32_t r[4];
                LDSM4(r, rb);
                bh[2 * np][0]     = r[0]; bh[2 * np][1]     = r[1];
                bh[2 * np + 1][0] = r[2]; bh[2 * np + 1][1] = r[3];
                LDSM4(r, rb + TILE_B);
                bl[2 * np][0]     = r[0]; bl[2 * np][1]     = r[1];
                bl[2 * np + 1][0] = r[2]; bl[2 * np + 1][1] = r[3];
            }
            #pragma unroll
            for (int mt = 0; mt < 4; mt++)
                #pragma unroll
                for (int nt = 0; nt < 4; nt++) {
                    mma16816(acc[mt][nt], ah[mt], bh[nt]);
                    mma16816(acc[mt][nt], ah[mt], bl[nt]);
                    mma16816(acc[mt][nt], al[mt], bh[nt]);
                }
        }
        __syncthreads();
    }

    const int g  = lane >> 2;
    const int t4 = lane & 3;
    #pragma unroll
    for (int mt = 0; mt < 4; mt++) {
        const size_t r0 = rowBase + wm * 64 + mt * 16 + g;
        #pragma unroll
        for (int nt = 0; nt < 4; nt++) {
            const size_t cc = colBase + wn * 32 + nt * 8 + t4 * 2;
            const float b0 = bias[cc], b1 = bias[cc + 1];
            float2 v0, v1;
            v0.x = acc[mt][nt][0] + b0; v0.y = acc[mt][nt][1] + b1;
            v1.x = acc[mt][nt][2] + b0; v1.y = acc[mt][nt][3] + b1;
            *(float2*)&C[r0 * Nn + cc]       = v0;
            *(float2*)&C[(r0 + 8) * Nn + cc] = v1;
        }
    }
}

// ---------------- HMMA flash attention, split-bf16 both GEMMs -------------
// CTA: 128 queries x (b,h); 8 warps x 16 q-rows, full 128-key width per warp.
// K loop: 16 blocks of 128 keys, K/V hi+lo double-buffered via cp.async.
#define ATILE  (128 * ROWB)        // 18432 B
#define ASTAGE (4 * ATILE)         // Kh, Kl, Vh, Vl
#define MHA_SMEM (2 * ATILE + 2 * ASTAGE)   // 184320 B

__global__ __launch_bounds__(256, 1) void mha_mma(
    const __nv_bfloat16* __restrict__ qh, const __nv_bfloat16* __restrict__ ql,
    const __nv_bfloat16* __restrict__ kh, const __nv_bfloat16* __restrict__ kl,
    const __nv_bfloat16* __restrict__ vh, const __nv_bfloat16* __restrict__ vl,
    __nv_bfloat16* __restrict__ ah, __nv_bfloat16* __restrict__ al)
{
    extern __shared__ char smem[];
    const uint32_t sb = smem_u32(smem);
    const int tid  = threadIdx.x;
    const int wid  = tid >> 5;
    const int lane = tid & 31;

    const int qtile = blockIdx.x;          // 0..15
    const int bh    = blockIdx.y;          // 0..31
    const size_t base = (size_t)bh * SEQ * HD;

    const int lr = tid >> 3;               // 0..31
    const int lj = tid & 7;                // 16B chunk

    // ---- load Q hi/lo tiles (group 0) ----
    {
        const __nv_bfloat16* qsrc[2] = { qh + base, ql + base };
        #pragma unroll
        for (int it = 0; it < 8; it++) {
            const int t = it >> 2;
            const int r = lr + (it & 3) * 32;
            const uint32_t dst = sb + t * ATILE + r * ROWB + lj * 16;
            cp_async16(dst, qsrc[t] + (size_t)(qtile * 128 + r) * HD + lj * 8);
        }
        CP_COMMIT();
    }

    const __nv_bfloat16* kvsrc[4] = { kh + base, kl + base, vh + base, vl + base };
    auto load_kv = [&](int kb, int stage) {
        const uint32_t st = sb + 2 * ATILE + stage * ASTAGE;
        #pragma unroll
        for (int it = 0; it < 16; it++) {
            const int t = it >> 2;
            const int r = lr + (it & 3) * 32;
            const uint32_t dst = st + t * ATILE + r * ROWB + lj * 16;
            cp_async16(dst, kvsrc[t] + (size_t)(kb * 128 + r) * HD + lj * 8);
        }
        CP_COMMIT();
    };
    load_kv(0, 0);

    // ---- Q fragments, register-resident for whole K loop ----
    const int arow = ((lane >> 3) & 1) * 8 + (lane & 7);
    const int acol = ((lane >> 4) & 1) * 8;
    const int brow = ((lane >> 4) & 1) * 8 + (lane & 7);
    const int bcol = ((lane >> 3) & 1) * 8;
    const int vrow = ((lane >> 3) & 1) * 8 + (lane & 7);   // key row (trans)
    const int vcol = ((lane >> 4) & 1) * 8;                // d col

    CP_WAIT(1);                 // Q group done (stage0 may be pending)
    __syncthreads();

    uint32_t qfh[4][4], qfl[4][4];
    #pragma unroll
    for (int kk = 0; kk < 4; kk++) {
        const uint32_t ra = sb + (wid * 16 + arow) * ROWB + (kk * 16 + acol) * 2;
        LDSM4(qfh[kk], ra);
        LDSM4(qfl[kk], ra + ATILE);
    }

    float oacc[8][4];
    #pragma unroll
    for (int i = 0; i < 8; i++)
        #pragma unroll
        for (int j = 0; j < 4; j++) oacc[i][j] = 0.f;
    float m0 = -1e30f, m1 = -1e30f, l0 = 0.f, l1 = 0.f;

    for (int kb = 0; kb < SEQ / 128; kb++) {
        const int s = kb & 1;
        if (kb + 1 < SEQ / 128) { load_kv(kb + 1, s ^ 1); CP_WAIT(1); }
        else                    { CP_WAIT(0); }
        __syncthreads();

        const uint32_t stK = sb + 2 * ATILE + s * ASTAGE;
        const uint32_t stV = stK + 2 * ATILE;

        // ---- S = Qs K^T (split, 3 terms) ----
        float sacc[16][4];
        #pragma unroll
        for (int t = 0; t < 16; t++)
            #pragma unroll
            for (int j = 0; j < 4; j++) sacc[t][j] = 0.f;

        #pragma unroll
        for (int np = 0; np < 8; np++) {
            #pragma unroll
            for (int kk = 0; kk < 4; kk++) {
                const uint32_t rK = stK + (np * 16 + brow) * ROWB
                                        + (kk * 16 + bcol) * 2;
                uint32_t rh[4], rl[4];
                LDSM4(rh, rK);
                LDSM4(rl, rK + ATILE);
                mma16816(sacc[2 * np],     qfh[kk], &rh[0]);
                mma16816(sacc[2 * np],     qfl[kk], &rh[0]);
                mma16816(sacc[2 * np],     qfh[kk], &rl[0]);
                mma16816(sacc[2 * np + 1], qfh[kk], &rh[2]);
                mma16816(sacc[2 * np + 1], qfl[kk], &rh[2]);
                mma16816(sacc[2 * np + 1], qfh[kk], &rl[2]);
            }
        }

        // ---- online softmax (base-2; q pre-scaled by 0.125*log2e) ----
        float tm0 = -1e30f, tm1 = -1e30f;
        #pragma unroll
        for (int t = 0; t < 16; t++) {
            tm0 = fmaxf(tm0, fmaxf(sacc[t][0], sacc[t][1]));
            tm1 = fmaxf(tm1, fmaxf(sacc[t][2], sacc[t][3]));
        }
        tm0 = fmaxf(tm0, __shfl_xor_sync(0xFFFFFFFFu, tm0, 1));
        tm0 = fmaxf(tm0, __shfl_xor_sync(0xFFFFFFFFu, tm0, 2));
        tm1 = fmaxf(tm1, __shfl_xor_sync(0xFFFFFFFFu, tm1, 1));
        tm1 = fmaxf(tm1, __shfl_xor_sync(0xFFFFFFFFu, tm1, 2));

        const float nm0 = fmaxf(m0, tm0);
        const float nm1 = fmaxf(m1, tm1);
        const float a0 = ex2f(m0 - nm0);
        const float a1 = ex2f(m1 - nm1);
        m0 = nm0; m1 = nm1;

        float rs0 = 0.f, rs1 = 0.f;
        #pragma unroll
        for (int t = 0; t < 16; t++) {
            sacc[t][0] = ex2f(sacc[t][0] - nm0);
            sacc[t][1] = ex2f(sacc[t][1] - nm0);
            sacc[t][2] = ex2f(sacc[t][2] - nm1);
            sacc[t][3] = ex2f(sacc[t][3] - nm1);
            rs0 += sacc[t][0] + sacc[t][1];
            rs1 += sacc[t][2] + sacc[t][3];
        }
        rs0 += __shfl_xor_sync(0xFFFFFFFFu, rs0, 1);
        rs0 += __shfl_xor_sync(0xFFFFFFFFu, rs0, 2);
        rs1 += __shfl_xor_sync(0xFFFFFFFFu, rs1, 1);
        rs1 += __shfl_xor_sync(0xFFFFFFFFu, rs1, 2);
        l0 = l0 * a0 + rs0;
        l1 = l1 * a1 + rs1;

        #pragma unroll
        for (int nt = 0; nt < 8; nt++) {
            oacc[nt][0] *= a0; oacc[nt][1] *= a0;
            oacc[nt][2] *= a1; oacc[nt][3] *= a1;
        }

        // ---- O += Ps V (split, 3 terms); P frags built from sacc in regs ----
        #pragma unroll
        for (int kc = 0; kc < 8; kc++) {
            const int t0 = 2 * kc, t1 = 2 * kc + 1;
            uint32_t pah[4], pal[4];
            {
                float h00 = bf16rt(sacc[t0][0]), h01 = bf16rt(sacc[t0][1]);
                float h02 = bf16rt(sacc[t0][2]), h03 = bf16rt(sacc[t0][3]);
                float h10 = bf16rt(sacc[t1][0]), h11 = bf16rt(sacc[t1][1]);
                float h12 = bf16rt(sacc[t1][2]), h13 = bf16rt(sacc[t1][3]);
                pah[0] = pack_bf16x2(h00, h01);
                pah[1] = pack_bf16x2(h02, h03);
                pah[2] = pack_bf16x2(h10, h11);
                pah[3] = pack_bf16x2(h12, h13);
                pal[0] = pack_bf16x2(sacc[t0][0] - h00, sacc[t0][1] - h01);
                pal[1] = pack_bf16x2(sacc[t0][2] - h02, sacc[t0][3] - h03);
                pal[2] = pack_bf16x2(sacc[t1][0] - h10, sacc[t1][1] - h11);
                pal[3] = pack_bf16x2(sacc[t1][2] - h12, sacc[t1][3] - h13);
            }
            #pragma unroll
            for (int nv = 0; nv < 4; nv++) {
                const uint32_t rV = stV + (kc * 16 + vrow) * ROWB
                                        + (nv * 16 + vcol) * 2;
                uint32_t vh_[4], vl_[4];
                LDSM4T(vh_, rV);
                LDSM4T(vl_, rV + ATILE);
                mma16816(oacc[2 * nv],     pah, &vh_[0]);
                mma16816(oacc[2 * nv],     pal, &vh_[0]);
                mma16816(oacc[2 * nv],     pah, &vl_[0]);
                mma16816(oacc[2 * nv + 1], pah, &vh_[2]);
                mma16816(oacc[2 * nv + 1], pal, &vh_[2]);
                mma16816(oacc[2 * nv + 1], pah, &vl_[2]);
            }
        }
        __syncthreads();
    }

    // ---- epilogue: normalize, split hi/lo, write to g_ah / g_al ----
    const int g  = lane >> 2;
    const int t4 = lane & 3;
    const float inv0 = 1.f / l0;
    const float inv1 = 1.f / l1;
    const int b = bh >> 4, h = bh & 15;
    const size_t tok0 = (size_t)b * SEQ + qtile * 128 + wid * 16 + g;
    const int colb = h * HD;
    #pragma unroll
    for (int nt = 0; nt < 8; nt++) {
        const int cc = colb + nt * 8 + 2 * t4;
        float x0 = oacc[nt][0] * inv0, x1 = oacc[nt][1] * inv0;
        float y0 = oacc[nt][2] * inv1, y1 = oacc[nt][3] * inv1;
        float hx0 = bf16rt(x0), hx1 = bf16rt(x1);
        float hy0 = bf16rt(y0), hy1 = bf16rt(y1);
        *(uint32_t*)&ah[tok0 * EMB + cc]       = pack_bf16x2(hx0, hx1);
        *(uint32_t*)&al[tok0 * EMB + cc]       = pack_bf16x2(x0 - hx0, x1 - hx1);
        *(uint32_t*)&ah[(tok0 + 8) * EMB + cc] = pack_bf16x2(hy0, hy1);
        *(uint32_t*)&al[(tok0 + 8) * EMB + cc] = pack_bf16x2(y0 - hy0, y1 - hy1);
    }
}

// ---------------------------------------------------------------------------
extern "C" void kernel_launch(void* const* d_in, const int* in_sizes, int n_in,
                              void* d_out, int out_size)
{
    const float* x     = (const float*)d_in[0];
    const float* w_in  = (const float*)d_in[1];
    const float* b_in  = (const float*)d_in[2];
    const float* w_out = (const float*)d_in[3];
    const float* b_out = (const float*)d_in[4];
    float* out = (float*)d_out;

    float* qkv;
    __nv_bfloat16 *xh, *xl, *wih, *wil, *woh, *wol, *ah, *al;
    __nv_bfloat16 *qh, *ql, *kh, *kl, *vh, *vl;
    cudaGetSymbolAddress((void**)&qkv, g_qkv);
    cudaGetSymbolAddress((void**)&xh,  g_xh);
    cudaGetSymbolAddress((void**)&xl,  g_xl);
    cudaGetSymbolAddress((void**)&wih, g_wih);
    cudaGetSymbolAddress((void**)&wil, g_wil);
    cudaGetSymbolAddress((void**)&woh, g_woh);
    cudaGetSymbolAddress((void**)&wol, g_wol);
    cudaGetSymbolAddress((void**)&ah,  g_ah);
    cudaGetSymbolAddress((void**)&al,  g_al);
    cudaGetSymbolAddress((void**)&qh,  g_qh);
    cudaGetSymbolAddress((void**)&ql,  g_ql);
    cudaGetSymbolAddress((void**)&kh,  g_kh);
    cudaGetSymbolAddress((void**)&kl,  g_kl);
    cudaGetSymbolAddress((void**)&vh,  g_vh);
    cudaGetSymbolAddress((void**)&vl,  g_vl);

    cudaFuncSetAttribute(mma_gemm,
                         cudaFuncAttributeMaxDynamicSharedMemorySize, GEMM_SMEM);
    cudaFuncSetAttribute(mha_mma,
                         cudaFuncAttributeMaxDynamicSharedMemorySize, MHA_SMEM);

    // 0) fp32 -> bf16 hi/lo splits for GEMM operands
    {
        int n4;
        n4 = TOK * EMB / 4; split_bf16<<<(n4 + 255) / 256, 256>>>(x,     xh,  xl,  n4);
        n4 = E3  * EMB / 4; split_bf16<<<(n4 + 255) / 256, 256>>>(w_in,  wih, wil, n4);
        n4 = EMB * EMB / 4; split_bf16<<<(n4 + 255) / 256, 256>>>(w_out, woh, wol, n4);
    }

    // 1) QKV projection on HMMA: [4096,3072]
    mma_gemm<<<dim3(E3 / 128, TOK / 128), 256, GEMM_SMEM>>>(
        xh, xl, wih, wil, b_in, qkv, E3, EMB);

    // 2) reshape+split qkv into per-(b,h) bf16 hi/lo q/k/v
    {
        int n = TOK * E3 / 4;
        split_qkv<<<(n + 255) / 256, 256>>>(qkv, qh, ql, kh, kl, vh, vl);
    }

    // 3) HMMA flash attention -> ah/al (bf16 hi/lo, [tok][EMB])
    mha_mma<<<dim3(SEQ / 128, 2 * NH), 256, MHA_SMEM>>>(
        qh, ql, kh, kl, vh, vl, ah, al);

    // 4) out-projection on HMMA: [4096,1024]
    mma_gemm<<<dim3(EMB / 128, TOK / 128), 256, GEMM_SMEM>>>(
        ah, al, woh, wol, b_out, out, EMB, EMB);
}

// round 7
// speedup vs baseline: 3.3049x; 1.0466x over previous
#include <cuda_runtime.h>
#include <cuda_bf16.h>
#include <cstdint>

#define TOK 4096
#define SEQ 2048
#define EMB 1024
#define E3  3072
#define NH  16
#define HD  64

// ---------------- scratch (cudaMalloc forbidden) ----------------
__device__ __nv_bfloat16 g_xh[(size_t)TOK * EMB],  g_xl[(size_t)TOK * EMB];
__device__ __nv_bfloat16 g_wih[(size_t)E3 * EMB],  g_wil[(size_t)E3 * EMB];
__device__ __nv_bfloat16 g_woh[(size_t)EMB * EMB], g_wol[(size_t)EMB * EMB];
__device__ __nv_bfloat16 g_ah[(size_t)TOK * EMB],  g_al[(size_t)TOK * EMB];
// per-(b,h) contiguous q/k/v splits: [B*NH][SEQ][HD]
__device__ __nv_bfloat16 g_qh[(size_t)TOK * EMB], g_ql[(size_t)TOK * EMB];
__device__ __nv_bfloat16 g_kh[(size_t)TOK * EMB], g_kl[(size_t)TOK * EMB];
__device__ __nv_bfloat16 g_vh[(size_t)TOK * EMB], g_vl[(size_t)TOK * EMB];

// ---------------- helpers ----------------
__device__ __forceinline__ uint32_t smem_u32(const void* p) {
    uint32_t a;
    asm("{ .reg .u64 t; cvta.to.shared.u64 t, %1; cvt.u32.u64 %0, t; }"
        : "=r"(a) : "l"(p));
    return a;
}
__device__ __forceinline__ void cp_async16(uint32_t dst, const void* src) {
    asm volatile("cp.async.cg.shared.global [%0], [%1], 16;"
                 :: "r"(dst), "l"(src));
}
#define CP_COMMIT()  asm volatile("cp.async.commit_group;" ::: "memory")
#define CP_WAIT(n)   asm volatile("cp.async.wait_group %0;" :: "n"(n) : "memory")

#define LDSM4(r, a)                                                         \
    asm volatile("ldmatrix.sync.aligned.m8n8.x4.shared.b16 "                \
                 "{%0,%1,%2,%3}, [%4];"                                     \
                 : "=r"((r)[0]), "=r"((r)[1]), "=r"((r)[2]), "=r"((r)[3])   \
                 : "r"(a))
#define LDSM4T(r, a)                                                        \
    asm volatile("ldmatrix.sync.aligned.m8n8.x4.trans.shared.b16 "          \
                 "{%0,%1,%2,%3}, [%4];"                                     \
                 : "=r"((r)[0]), "=r"((r)[1]), "=r"((r)[2]), "=r"((r)[3])   \
                 : "r"(a))

__device__ __forceinline__ void mma16816(float* d, const uint32_t* a,
                                         const uint32_t* b) {
    asm volatile(
        "mma.sync.aligned.m16n8k16.row.col.f32.bf16.bf16.f32 "
        "{%0,%1,%2,%3}, {%4,%5,%6,%7}, {%8,%9}, {%0,%1,%2,%3};"
        : "+f"(d[0]), "+f"(d[1]), "+f"(d[2]), "+f"(d[3])
        : "r"(a[0]), "r"(a[1]), "r"(a[2]), "r"(a[3]), "r"(b[0]), "r"(b[1]));
}
__device__ __forceinline__ float ex2f(float x) {
    float y; asm("ex2.approx.ftz.f32 %0, %1;" : "=f"(y) : "f"(x)); return y;
}
__device__ __forceinline__ uint32_t pack_bf16x2(float lo, float hi) {
    uint32_t r;
    asm("cvt.rn.bf16x2.f32 %0, %1, %2;" : "=r"(r) : "f"(hi), "f"(lo));
    return r;
}
__device__ __forceinline__ float bf16rt(float x) {
    return __bfloat162float(__float2bfloat16(x));
}

// ---------------- fp32 -> bf16 hi/lo split (generic) ----------------
__global__ __launch_bounds__(256) void split_bf16(
    const float* __restrict__ s, __nv_bfloat16* __restrict__ h,
    __nv_bfloat16* __restrict__ l, int n4)
{
    int i = blockIdx.x * blockDim.x + threadIdx.x;
    if (i >= n4) return;
    float4 v = ((const float4*)s)[i];
    float hx = bf16rt(v.x), hy = bf16rt(v.y), hz = bf16rt(v.z), hw = bf16rt(v.w);
    *(uint32_t*)&h[4 * (size_t)i]     = pack_bf16x2(hx, hy);
    *(uint32_t*)&h[4 * (size_t)i + 2] = pack_bf16x2(hz, hw);
    *(uint32_t*)&l[4 * (size_t)i]     = pack_bf16x2(v.x - hx, v.y - hy);
    *(uint32_t*)&l[4 * (size_t)i + 2] = pack_bf16x2(v.z - hz, v.w - hw);
}

// ---------------- split-bf16 GEMM, 128x256 CTA tile, fusable epilogue -----
// mode 0: C = A@B^T + bias (fp32).  mode 1: QKV epilogue -> per-(b,h) bf16
// hi/lo q/k/v (q pre-scaled by 0.125*log2e).
#define QSCALE 0.18033688011112042f
#define KC     64
#define ROWB   144
#define OFF_AL (128 * ROWB)          // 18432
#define OFF_BH (2 * 128 * ROWB)      // 36864
#define OFF_BL (OFF_BH + 256 * ROWB) // 73728
#define STAGE_B (OFF_BH + 2 * 256 * ROWB)   // 110592
#define GEMM_SMEM (2 * STAGE_B)             // 221184

__global__ __launch_bounds__(256, 1) void mma_gemm(
    const __nv_bfloat16* __restrict__ Ah, const __nv_bfloat16* __restrict__ Al,
    const __nv_bfloat16* __restrict__ Bh, const __nv_bfloat16* __restrict__ Bl,
    const float* __restrict__ bias, float* __restrict__ C,
    __nv_bfloat16* __restrict__ qh, __nv_bfloat16* __restrict__ ql,
    __nv_bfloat16* __restrict__ kh, __nv_bfloat16* __restrict__ kl,
    __nv_bfloat16* __restrict__ vh, __nv_bfloat16* __restrict__ vl,
    int Nn, int K, int mode)
{
    extern __shared__ char smem[];
    const uint32_t sb = smem_u32(smem);
    const int tid  = threadIdx.x;
    const int wid  = tid >> 5;
    const int lane = tid & 31;
    const int wm = wid >> 2;            // 0..1 (64 rows)
    const int wn = wid & 3;             // 0..3 (64 cols)

    const size_t rowBase = (size_t)blockIdx.y * 128;
    const size_t colBase = (size_t)blockIdx.x * 256;

    const __nv_bfloat16* sAh = Ah + rowBase * K;
    const __nv_bfloat16* sAl = Al + rowBase * K;
    const __nv_bfloat16* sBh = Bh + colBase * K;
    const __nv_bfloat16* sBl = Bl + colBase * K;

    const int r0l = tid >> 3;           // 0..31
    const int lj  = tid & 7;
    auto load_chunk = [&](int c, int stage) {
        const uint32_t st = sb + stage * STAGE_B;
        const int kof = c * KC + lj * 8;
        #pragma unroll
        for (int it = 0; it < 24; it++) {
            const int r = it * 32 + r0l;           // 0..767
            uint32_t dst; const __nv_bfloat16* src;
            if (it < 4)       { dst = st + r * ROWB + lj * 16;
                                src = sAh + (size_t)r * K + kof; }
            else if (it < 8)  { const int rr = r - 128;
                                dst = st + OFF_AL + rr * ROWB + lj * 16;
                                src = sAl + (size_t)rr * K + kof; }
            else if (it < 16) { const int rr = r - 256;
                                dst = st + OFF_BH + rr * ROWB + lj * 16;
                                src = sBh + (size_t)rr * K + kof; }
            else              { const int rr = r - 512;
                                dst = st + OFF_BL + rr * ROWB + lj * 16;
                                src = sBl + (size_t)rr * K + kof; }
            cp_async16(dst, src);
        }
        CP_COMMIT();
    };

    float acc[4][8][4];
    #pragma unroll
    for (int i = 0; i < 4; i++)
        #pragma unroll
        for (int j = 0; j < 8; j++)
            #pragma unroll
            for (int k = 0; k < 4; k++) acc[i][j][k] = 0.f;

    const int arow = ((lane >> 3) & 1) * 8 + (lane & 7);
    const int acol = ((lane >> 4) & 1) * 8;
    const int brow = ((lane >> 4) & 1) * 8 + (lane & 7);
    const int bcol = ((lane >> 3) & 1) * 8;

    const int nch = K / KC;
    load_chunk(0, 0);

    for (int c = 0; c < nch; c++) {
        const int s = c & 1;
        if (c + 1 < nch) { load_chunk(c + 1, s ^ 1); CP_WAIT(1); }
        else             { CP_WAIT(0); }
        __syncthreads();

        const uint32_t stS = sb + s * STAGE_B;

        #pragma unroll
        for (int kk = 0; kk < 4; kk++) {
            const int k0 = kk * 16;
            uint32_t ahf[4][4], alf[4][4];
            #pragma unroll
            for (int mt = 0; mt < 4; mt++) {
                const uint32_t ra = stS + (wm * 64 + mt * 16 + arow) * ROWB
                                        + (k0 + acol) * 2;
                LDSM4(ahf[mt], ra);
                LDSM4(alf[mt], ra + OFF_AL);
            }
            #pragma unroll
            for (int nh = 0; nh < 2; nh++) {
                uint32_t bhf[4][2], blf[4][2];
                #pragma unroll
                for (int np = 0; np < 2; np++) {
                    const uint32_t rb = stS + OFF_BH
                        + (wn * 64 + (nh * 2 + np) * 16 + brow) * ROWB
                        + (k0 + bcol) * 2;
                    uint32_t r[4];
                    LDSM4(r, rb);
                    bhf[2 * np][0]     = r[0]; bhf[2 * np][1]     = r[1];
                    bhf[2 * np + 1][0] = r[2]; bhf[2 * np + 1][1] = r[3];
                    LDSM4(r, rb + (OFF_BL - OFF_BH));
                    blf[2 * np][0]     = r[0]; blf[2 * np][1]     = r[1];
                    blf[2 * np + 1][0] = r[2]; blf[2 * np + 1][1] = r[3];
                }
                #pragma unroll
                for (int mt = 0; mt < 4; mt++)
                    #pragma unroll
                    for (int nt = 0; nt < 4; nt++) {
                        float* a = acc[mt][nh * 4 + nt];
                        mma16816(a, ahf[mt], bhf[nt]);
                        mma16816(a, ahf[mt], blf[nt]);
                        mma16816(a, alf[mt], bhf[nt]);
                    }
            }
        }
        __syncthreads();
    }

    // ---- epilogue ----
    const int g  = lane >> 2;
    const int t4 = lane & 3;
    if (mode == 0) {
        #pragma unroll
        for (int mt = 0; mt < 4; mt++) {
            const size_t r0 = rowBase + wm * 64 + mt * 16 + g;
            #pragma unroll
            for (int nt = 0; nt < 8; nt++) {
                const size_t cc = colBase + wn * 64 + nt * 8 + t4 * 2;
                const float b0 = bias[cc], b1 = bias[cc + 1];
                float2 v0, v1;
                v0.x = acc[mt][nt][0] + b0; v0.y = acc[mt][nt][1] + b1;
                v1.x = acc[mt][nt][2] + b0; v1.y = acc[mt][nt][3] + b1;
                *(float2*)&C[r0 * Nn + cc]       = v0;
                *(float2*)&C[(r0 + 8) * Nn + cc] = v1;
            }
        }
    } else {
        #pragma unroll
        for (int mt = 0; mt < 4; mt++) {
            const int tok0 = (int)rowBase + wm * 64 + mt * 16 + g;
            #pragma unroll
            for (int nt = 0; nt < 8; nt++) {
                const int cc = (int)colBase + wn * 64 + nt * 8 + t4 * 2;
                const int sec = cc >> 10;            // 0=q 1=k 2=v
                const int rest = cc & 1023;
                const int h = rest >> 6, d = rest & 63;
                float v00 = acc[mt][nt][0] + bias[cc];
                float v01 = acc[mt][nt][1] + bias[cc + 1];
                float v10 = acc[mt][nt][2] + bias[cc];
                float v11 = acc[mt][nt][3] + bias[cc + 1];
                __nv_bfloat16 *ph, *pl;
                if (sec == 0) {
                    ph = qh; pl = ql;
                    v00 *= QSCALE; v01 *= QSCALE; v10 *= QSCALE; v11 *= QSCALE;
                } else if (sec == 1) { ph = kh; pl = kl; }
                else                 { ph = vh; pl = vl; }
                const size_t o0 = (((size_t)((tok0 >> 11) * NH + h)) * SEQ
                                   + (tok0 & 2047)) * HD + d;
                const size_t o1 = o0 + 8 * HD;       // row tok0+8, same (b,h)
                float h00 = bf16rt(v00), h01 = bf16rt(v01);
                float h10 = bf16rt(v10), h11 = bf16rt(v11);
                *(uint32_t*)&ph[o0] = pack_bf16x2(h00, h01);
                *(uint32_t*)&pl[o0] = pack_bf16x2(v00 - h00, v01 - h01);
                *(uint32_t*)&ph[o1] = pack_bf16x2(h10, h11);
                *(uint32_t*)&pl[o1] = pack_bf16x2(v10 - h10, v11 - h11);
            }
        }
    }
}

// ---------------- HMMA flash attention (round-4, validated) ---------------
#define ATILE  (128 * ROWB)
#define ASTAGE (4 * ATILE)
#define MHA_SMEM (2 * ATILE + 2 * ASTAGE)   // 184320 B

__global__ __launch_bounds__(256, 1) void mha_mma(
    const __nv_bfloat16* __restrict__ qh, const __nv_bfloat16* __restrict__ ql,
    const __nv_bfloat16* __restrict__ kh, const __nv_bfloat16* __restrict__ kl,
    const __nv_bfloat16* __restrict__ vh, const __nv_bfloat16* __restrict__ vl,
    __nv_bfloat16* __restrict__ ah, __nv_bfloat16* __restrict__ al)
{
    extern __shared__ char smem[];
    const uint32_t sb = smem_u32(smem);
    const int tid  = threadIdx.x;
    const int wid  = tid >> 5;
    const int lane = tid & 31;

    const int qtile = blockIdx.x;
    const int bh    = blockIdx.y;
    const size_t base = (size_t)bh * SEQ * HD;

    const int lr = tid >> 3;
    const int lj = tid & 7;

    {
        const __nv_bfloat16* qsrc[2] = { qh + base, ql + base };
        #pragma unroll
        for (int it = 0; it < 8; it++) {
            const int t = it >> 2;
            const int r = lr + (it & 3) * 32;
            const uint32_t dst = sb + t * ATILE + r * ROWB + lj * 16;
            cp_async16(dst, qsrc[t] + (size_t)(qtile * 128 + r) * HD + lj * 8);
        }
        CP_COMMIT();
    }

    const __nv_bfloat16* kvsrc[4] = { kh + base, kl + base, vh + base, vl + base };
    auto load_kv = [&](int kb, int stage) {
        const uint32_t st = sb + 2 * ATILE + stage * ASTAGE;
        #pragma unroll
        for (int it = 0; it < 16; it++) {
            const int t = it >> 2;
            const int r = lr + (it & 3) * 32;
            const uint32_t dst = st + t * ATILE + r * ROWB + lj * 16;
            cp_async16(dst, kvsrc[t] + (size_t)(kb * 128 + r) * HD + lj * 8);
        }
        CP_COMMIT();
    };
    load_kv(0, 0);

    const int arow = ((lane >> 3) & 1) * 8 + (lane & 7);
    const int acol = ((lane >> 4) & 1) * 8;
    const int brow = ((lane >> 4) & 1) * 8 + (lane & 7);
    const int bcol = ((lane >> 3) & 1) * 8;
    const int vrow = ((lane >> 3) & 1) * 8 + (lane & 7);
    const int vcol = ((lane >> 4) & 1) * 8;

    CP_WAIT(1);
    __syncthreads();

    uint32_t qfh[4][4], qfl[4][4];
    #pragma unroll
    for (int kk = 0; kk < 4; kk++) {
        const uint32_t ra = sb + (wid * 16 + arow) * ROWB + (kk * 16 + acol) * 2;
        LDSM4(qfh[kk], ra);
        LDSM4(qfl[kk], ra + ATILE);
    }

    float oacc[8][4];
    #pragma unroll
    for (int i = 0; i < 8; i++)
        #pragma unroll
        for (int j = 0; j < 4; j++) oacc[i][j] = 0.f;
    float m0 = -1e30f, m1 = -1e30f, l0 = 0.f, l1 = 0.f;

    for (int kb = 0; kb < SEQ / 128; kb++) {
        const int s = kb & 1;
        if (kb + 1 < SEQ / 128) { load_kv(kb + 1, s ^ 1); CP_WAIT(1); }
        else                    { CP_WAIT(0); }
        __syncthreads();

        const uint32_t stK = sb + 2 * ATILE + s * ASTAGE;
        const uint32_t stV = stK + 2 * ATILE;

        float sacc[16][4];
        #pragma unroll
        for (int t = 0; t < 16; t++)
            #pragma unroll
            for (int j = 0; j < 4; j++) sacc[t][j] = 0.f;

        #pragma unroll
        for (int np = 0; np < 8; np++) {
            #pragma unroll
            for (int kk = 0; kk < 4; kk++) {
                const uint32_t rK = stK + (np * 16 + brow) * ROWB
                                        + (kk * 16 + bcol) * 2;
                uint32_t rh[4], rl[4];
                LDSM4(rh, rK);
                LDSM4(rl, rK + ATILE);
                mma16816(sacc[2 * np],     qfh[kk], &rh[0]);
                mma16816(sacc[2 * np],     qfl[kk], &rh[0]);
                mma16816(sacc[2 * np],     qfh[kk], &rl[0]);
                mma16816(sacc[2 * np + 1], qfh[kk], &rh[2]);
                mma16816(sacc[2 * np + 1], qfl[kk], &rh[2]);
                mma16816(sacc[2 * np + 1], qfh[kk], &rl[2]);
            }
        }

        float tm0 = -1e30f, tm1 = -1e30f;
        #pragma unroll
        for (int t = 0; t < 16; t++) {
            tm0 = fmaxf(tm0, fmaxf(sacc[t][0], sacc[t][1]));
            tm1 = fmaxf(tm1, fmaxf(sacc[t][2], sacc[t][3]));
        }
        tm0 = fmaxf(tm0, __shfl_xor_sync(0xFFFFFFFFu, tm0, 1));
        tm0 = fmaxf(tm0, __shfl_xor_sync(0xFFFFFFFFu, tm0, 2));
        tm1 = fmaxf(tm1, __shfl_xor_sync(0xFFFFFFFFu, tm1, 1));
        tm1 = fmaxf(tm1, __shfl_xor_sync(0xFFFFFFFFu, tm1, 2));

        const float nm0 = fmaxf(m0, tm0);
        const float nm1 = fmaxf(m1, tm1);
        const float a0 = ex2f(m0 - nm0);
        const float a1 = ex2f(m1 - nm1);
        m0 = nm0; m1 = nm1;

        float rs0 = 0.f, rs1 = 0.f;
        #pragma unroll
        for (int t = 0; t < 16; t++) {
            sacc[t][0] = ex2f(sacc[t][0] - nm0);
            sacc[t][1] = ex2f(sacc[t][1] - nm0);
            sacc[t][2] = ex2f(sacc[t][2] - nm1);
            sacc[t][3] = ex2f(sacc[t][3] - nm1);
            rs0 += sacc[t][0] + sacc[t][1];
            rs1 += sacc[t][2] + sacc[t][3];
        }
        rs0 += __shfl_xor_sync(0xFFFFFFFFu, rs0, 1);
        rs0 += __shfl_xor_sync(0xFFFFFFFFu, rs0, 2);
        rs1 += __shfl_xor_sync(0xFFFFFFFFu, rs1, 1);
        rs1 += __shfl_xor_sync(0xFFFFFFFFu, rs1, 2);
        l0 = l0 * a0 + rs0;
        l1 = l1 * a1 + rs1;

        #pragma unroll
        for (int nt = 0; nt < 8; nt++) {
            oacc[nt][0] *= a0; oacc[nt][1] *= a0;
            oacc[nt][2] *= a1; oacc[nt][3] *= a1;
        }

        #pragma unroll
        for (int kc = 0; kc < 8; kc++) {
            const int t0 = 2 * kc, t1 = 2 * kc + 1;
            uint32_t pah[4], pal[4];
            {
                float h00 = bf16rt(sacc[t0][0]), h01 = bf16rt(sacc[t0][1]);
                float h02 = bf16rt(sacc[t0][2]), h03 = bf16rt(sacc[t0][3]);
                float h10 = bf16rt(sacc[t1][0]), h11 = bf16rt(sacc[t1][1]);
                float h12 = bf16rt(sacc[t1][2]), h13 = bf16rt(sacc[t1][3]);
                pah[0] = pack_bf16x2(h00, h01);
                pah[1] = pack_bf16x2(h02, h03);
                pah[2] = pack_bf16x2(h10, h11);
                pah[3] = pack_bf16x2(h12, h13);
                pal[0] = pack_bf16x2(sacc[t0][0] - h00, sacc[t0][1] - h01);
                pal[1] = pack_bf16x2(sacc[t0][2] - h02, sacc[t0][3] - h03);
                pal[2] = pack_bf16x2(sacc[t1][0] - h10, sacc[t1][1] - h11);
                pal[3] = pack_bf16x2(sacc[t1][2] - h12, sacc[t1][3] - h13);
            }
            #pragma unroll
            for (int nv = 0; nv < 4; nv++) {
                const uint32_t rV = stV + (kc * 16 + vrow) * ROWB
                                        + (nv * 16 + vcol) * 2;
                uint32_t vh_[4], vl_[4];
                LDSM4T(vh_, rV);
                LDSM4T(vl_, rV + ATILE);
                mma16816(oacc[2 * nv],     pah, &vh_[0]);
                mma16816(oacc[2 * nv],     pal, &vh_[0]);
                mma16816(oacc[2 * nv],     pah, &vl_[0]);
                mma16816(oacc[2 * nv + 1], pah, &vh_[2]);
                mma16816(oacc[2 * nv + 1], pal, &vh_[2]);
                mma16816(oacc[2 * nv + 1], pah, &vl_[2]);
            }
        }
        __syncthreads();
    }

    const int g  = lane >> 2;
    const int t4 = lane & 3;
    const float inv0 = 1.f / l0;
    const float inv1 = 1.f / l1;
    const int b = bh >> 4, h = bh & 15;
    const size_t tok0 = (size_t)b * SEQ + qtile * 128 + wid * 16 + g;
    const int colb = h * HD;
    #pragma unroll
    for (int nt = 0; nt < 8; nt++) {
        const int cc = colb + nt * 8 + 2 * t4;
        float x0 = oacc[nt][0] * inv0, x1 = oacc[nt][1] * inv0;
        float y0 = oacc[nt][2] * inv1, y1 = oacc[nt][3] * inv1;
        float hx0 = bf16rt(x0), hx1 = bf16rt(x1);
        float hy0 = bf16rt(y0), hy1 = bf16rt(y1);
        *(uint32_t*)&ah[tok0 * EMB + cc]       = pack_bf16x2(hx0, hx1);
        *(uint32_t*)&al[tok0 * EMB + cc]       = pack_bf16x2(x0 - hx0, x1 - hx1);
        *(uint32_t*)&ah[(tok0 + 8) * EMB + cc] = pack_bf16x2(hy0, hy1);
        *(uint32_t*)&al[(tok0 + 8) * EMB + cc] = pack_bf16x2(y0 - hy0, y1 - hy1);
    }
}

// ---------------------------------------------------------------------------
extern "C" void kernel_launch(void* const* d_in, const int* in_sizes, int n_in,
                              void* d_out, int out_size)
{
    const float* x     = (const float*)d_in[0];
    const float* w_in  = (const float*)d_in[1];
    const float* b_in  = (const float*)d_in[2];
    const float* w_out = (const float*)d_in[3];
    const float* b_out = (const float*)d_in[4];
    float* out = (float*)d_out;

    __nv_bfloat16 *xh, *xl, *wih, *wil, *woh, *wol, *ah, *al;
    __nv_bfloat16 *qh, *ql, *kh, *kl, *vh, *vl;
    cudaGetSymbolAddress((void**)&xh,  g_xh);
    cudaGetSymbolAddress((void**)&xl,  g_xl);
    cudaGetSymbolAddress((void**)&wih, g_wih);
    cudaGetSymbolAddress((void**)&wil, g_wil);
    cudaGetSymbolAddress((void**)&woh, g_woh);
    cudaGetSymbolAddress((void**)&wol, g_wol);
    cudaGetSymbolAddress((void**)&ah,  g_ah);
    cudaGetSymbolAddress((void**)&al,  g_al);
    cudaGetSymbolAddress((void**)&qh,  g_qh);
    cudaGetSymbolAddress((void**)&ql,  g_ql);
    cudaGetSymbolAddress((void**)&kh,  g_kh);
    cudaGetSymbolAddress((void**)&kl,  g_kl);
    cudaGetSymbolAddress((void**)&vh,  g_vh);
    cudaGetSymbolAddress((void**)&vl,  g_vl);

    cudaFuncSetAttribute(mma_gemm,
                         cudaFuncAttributeMaxDynamicSharedMemorySize, GEMM_SMEM);
    cudaFuncSetAttribute(mha_mma,
                         cudaFuncAttributeMaxDynamicSharedMemorySize, MHA_SMEM);

    // 0) fp32 -> bf16 hi/lo splits
    {
        int n4;
        n4 = TOK * EMB / 4; split_bf16<<<(n4 + 255) / 256, 256>>>(x,     xh,  xl,  n4);
        n4 = E3  * EMB / 4; split_bf16<<<(n4 + 255) / 256, 256>>>(w_in,  wih, wil, n4);
        n4 = EMB * EMB / 4; split_bf16<<<(n4 + 255) / 256, 256>>>(w_out, woh, wol, n4);
    }

    // 1) QKV projection, fused epilogue -> per-(b,h) bf16 hi/lo q/k/v
    mma_gemm<<<dim3(E3 / 256, TOK / 128), 256, GEMM_SMEM>>>(
        xh, xl, wih, wil, b_in, nullptr,
        qh, ql, kh, kl, vh, vl, E3, EMB, 1);

    // 2) HMMA flash attention -> ah/al
    mha_mma<<<dim3(SEQ / 128, 2 * NH), 256, MHA_SMEM>>>(
        qh, ql, kh, kl, vh, vl, ah, al);

    // 3) out-projection: [4096,1024] fp32 + bias (single wave: 128 CTAs)
    mma_gemm<<<dim3(EMB / 256, TOK / 128), 256, GEMM_SMEM>>>(
        ah, al, woh, wol, b_out, out,
        nullptr, nullptr, nullptr, nullptr, nullptr, nullptr, EMB, EMB, 0);
}

// round 11
// speedup vs baseline: 3.9022x; 1.1807x over previous
#include <cuda_runtime.h>
#include <cuda_bf16.h>
#include <cuda_fp16.h>
#include <cstdint>

#define TOK 4096
#define SEQ 2048
#define EMB 1024
#define E3  3072
#define NH  16
#define HD  64

// ---------------- scratch (cudaMalloc forbidden) ----------------
__device__ __half g_xh[(size_t)TOK * EMB], g_xl[(size_t)TOK * EMB];
__device__ __half g_wih[(size_t)E3 * EMB];          // w_in, single fp16
__device__ __half g_woh[(size_t)EMB * EMB];         // w_out, single fp16
__device__ __half g_ah[(size_t)TOK * EMB], g_al[(size_t)TOK * EMB];
// per-(b,h) contiguous q/k/v splits (bf16, attention unchanged): [B*NH][SEQ][HD]
__device__ __nv_bfloat16 g_qh[(size_t)TOK * EMB], g_ql[(size_t)TOK * EMB];
__device__ __nv_bfloat16 g_kh[(size_t)TOK * EMB], g_kl[(size_t)TOK * EMB];
__device__ __nv_bfloat16 g_vh[(size_t)TOK * EMB], g_vl[(size_t)TOK * EMB];

// ---------------- helpers ----------------
__device__ __forceinline__ uint32_t smem_u32(const void* p) {
    uint32_t a;
    asm("{ .reg .u64 t; cvta.to.shared.u64 t, %1; cvt.u32.u64 %0, t; }"
        : "=r"(a) : "l"(p));
    return a;
}
__device__ __forceinline__ void cp_async16(uint32_t dst, const void* src) {
    asm volatile("cp.async.cg.shared.global [%0], [%1], 16;"
                 :: "r"(dst), "l"(src));
}
#define CP_COMMIT()  asm volatile("cp.async.commit_group;" ::: "memory")
#define CP_WAIT(n)   asm volatile("cp.async.wait_group %0;" :: "n"(n) : "memory")

#define LDSM4(r, a)                                                         \
    asm volatile("ldmatrix.sync.aligned.m8n8.x4.shared.b16 "                \
                 "{%0,%1,%2,%3}, [%4];"                                     \
                 : "=r"((r)[0]), "=r"((r)[1]), "=r"((r)[2]), "=r"((r)[3])   \
                 : "r"(a))
#define LDSM4T(r, a)                                                        \
    asm volatile("ldmatrix.sync.aligned.m8n8.x4.trans.shared.b16 "          \
                 "{%0,%1,%2,%3}, [%4];"                                     \
                 : "=r"((r)[0]), "=r"((r)[1]), "=r"((r)[2]), "=r"((r)[3])   \
                 : "r"(a))

__device__ __forceinline__ void mma_bf16(float* d, const uint32_t* a,
                                         const uint32_t* b) {
    asm volatile(
        "mma.sync.aligned.m16n8k16.row.col.f32.bf16.bf16.f32 "
        "{%0,%1,%2,%3}, {%4,%5,%6,%7}, {%8,%9}, {%0,%1,%2,%3};"
        : "+f"(d[0]), "+f"(d[1]), "+f"(d[2]), "+f"(d[3])
        : "r"(a[0]), "r"(a[1]), "r"(a[2]), "r"(a[3]), "r"(b[0]), "r"(b[1]));
}
__device__ __forceinline__ void mma_f16(float* d, const uint32_t* a,
                                        const uint32_t* b) {
    asm volatile(
        "mma.sync.aligned.m16n8k16.row.col.f32.f16.f16.f32 "
        "{%0,%1,%2,%3}, {%4,%5,%6,%7}, {%8,%9}, {%0,%1,%2,%3};"
        : "+f"(d[0]), "+f"(d[1]), "+f"(d[2]), "+f"(d[3])
        : "r"(a[0]), "r"(a[1]), "r"(a[2]), "r"(a[3]), "r"(b[0]), "r"(b[1]));
}
__device__ __forceinline__ float ex2f(float x) {
    float y; asm("ex2.approx.ftz.f32 %0, %1;" : "=f"(y) : "f"(x)); return y;
}
__device__ __forceinline__ uint32_t pack_bf16x2(float lo, float hi) {
    uint32_t r;
    asm("cvt.rn.bf16x2.f32 %0, %1, %2;" : "=r"(r) : "f"(hi), "f"(lo));
    return r;
}
__device__ __forceinline__ float bf16rt(float x) {
    return __bfloat162float(__float2bfloat16(x));
}
__device__ __forceinline__ uint32_t pack_f16x2(float lo, float hi) {
    __half2 h = __floats2half2_rn(lo, hi);
    return *(uint32_t*)&h;
}
__device__ __forceinline__ float f16rt(float x) {
    return __half2float(__float2half_rn(x));
}

// ---------------- single prep kernel: all fp32 -> fp16 conversions --------
#define NX4  (TOK * EMB / 4)        // 1048576  x -> xh/xl (hi/lo)
#define NW14 (E3 * EMB / 4)         // 786432   w_in -> wih (single)
#define NW24 (EMB * EMB / 4)        // 262144   w_out -> woh (single)
#define NPREP (NX4 + NW14 + NW24)

__global__ __launch_bounds__(256) void prep(
    const float* __restrict__ x, const float* __restrict__ w_in,
    const float* __restrict__ w_out,
    __half* __restrict__ xh, __half* __restrict__ xl,
    __half* __restrict__ wih, __half* __restrict__ woh)
{
    int i = blockIdx.x * blockDim.x + threadIdx.x;
    if (i < NX4) {
        float4 v = ((const float4*)x)[i];
        float hx = f16rt(v.x), hy = f16rt(v.y), hz = f16rt(v.z), hw = f16rt(v.w);
        *(uint32_t*)&xh[4 * (size_t)i]     = pack_f16x2(hx, hy);
        *(uint32_t*)&xh[4 * (size_t)i + 2] = pack_f16x2(hz, hw);
        *(uint32_t*)&xl[4 * (size_t)i]     = pack_f16x2(v.x - hx, v.y - hy);
        *(uint32_t*)&xl[4 * (size_t)i + 2] = pack_f16x2(v.z - hz, v.w - hw);
    } else if (i < NX4 + NW14) {
        const int j = i - NX4;
        float4 v = ((const float4*)w_in)[j];
        *(uint32_t*)&wih[4 * (size_t)j]     = pack_f16x2(v.x, v.y);
        *(uint32_t*)&wih[4 * (size_t)j + 2] = pack_f16x2(v.z, v.w);
    } else if (i < NPREP) {
        const int j = i - NX4 - NW14;
        float4 v = ((const float4*)w_out)[j];
        *(uint32_t*)&woh[4 * (size_t)j]     = pack_f16x2(v.x, v.y);
        *(uint32_t*)&woh[4 * (size_t)j + 2] = pack_f16x2(v.z, v.w);
    }
}

// ---------------- fp16 GEMM: C = (Ah+Al) @ B^T (+bias) -------------------
// A-side 2-term fp16 split, B single fp16. 128x256 CTA tile, 8 warps 2x4,
// warp tile 64x64, KC=64 double-buffered.
// mode 0: fp32 C + bias.  mode 1: QKV epilogue -> per-(b,h) bf16 hi/lo q/k/v.
#define QSCALE 0.18033688011112042f
#define KC     64
#define ROWB   144
#define OFF_AL (128 * ROWB)                  // 18432
#define OFF_B  (2 * 128 * ROWB)              // 36864
#define STAGE_B (OFF_B + 256 * ROWB)         // 73728
#define GEMM_SMEM (2 * STAGE_B)              // 147456

__global__ __launch_bounds__(256, 1) void mma_gemm(
    const __half* __restrict__ Ah, const __half* __restrict__ Al,
    const __half* __restrict__ B,
    const float* __restrict__ bias, float* __restrict__ C,
    __nv_bfloat16* __restrict__ qh, __nv_bfloat16* __restrict__ ql,
    __nv_bfloat16* __restrict__ kh, __nv_bfloat16* __restrict__ kl,
    __nv_bfloat16* __restrict__ vh, __nv_bfloat16* __restrict__ vl,
    int Nn, int K, int mode)
{
    extern __shared__ char smem[];
    const uint32_t sb = smem_u32(smem);
    const int tid  = threadIdx.x;
    const int wid  = tid >> 5;
    const int lane = tid & 31;
    const int wm = wid >> 2;            // 0..1 (64 rows)
    const int wn = wid & 3;             // 0..3 (64 cols)

    const size_t rowBase = (size_t)blockIdx.y * 128;
    const size_t colBase = (size_t)blockIdx.x * 256;

    const __half* sAh = Ah + rowBase * K;
    const __half* sAl = Al + rowBase * K;
    const __half* sB  = B  + colBase * K;

    const int r0l = tid >> 3;           // 0..31
    const int lj  = tid & 7;
    auto load_chunk = [&](int c, int stage) {
        const uint32_t st = sb + stage * STAGE_B;
        const int kof = c * KC + lj * 8;
        #pragma unroll
        for (int it = 0; it < 16; it++) {
            const int r = it * 32 + r0l;           // 0..511
            uint32_t dst; const __half* src;
            if (it < 4)      { dst = st + r * ROWB + lj * 16;
                               src = sAh + (size_t)r * K + kof; }
            else if (it < 8) { const int rr = r - 128;
                               dst = st + OFF_AL + rr * ROWB + lj * 16;
                               src = sAl + (size_t)rr * K + kof; }
            else             { const int rr = r - 256;
                               dst = st + OFF_B + rr * ROWB + lj * 16;
                               src = sB + (size_t)rr * K + kof; }
            cp_async16(dst, src);
        }
        CP_COMMIT();
    };

    float acc[4][8][4];
    #pragma unroll
    for (int i = 0; i < 4; i++)
        #pragma unroll
        for (int j = 0; j < 8; j++)
            #pragma unroll
            for (int k = 0; k < 4; k++) acc[i][j][k] = 0.f;

    const int arow = ((lane >> 3) & 1) * 8 + (lane & 7);
    const int acol = ((lane >> 4) & 1) * 8;
    const int brow = ((lane >> 4) & 1) * 8 + (lane & 7);
    const int bcol = ((lane >> 3) & 1) * 8;

    const int nch = K / KC;
    load_chunk(0, 0);

    for (int c = 0; c < nch; c++) {
        const int s = c & 1;
        if (c + 1 < nch) { load_chunk(c + 1, s ^ 1); CP_WAIT(1); }
        else             { CP_WAIT(0); }
        __syncthreads();

        const uint32_t stS = sb + s * STAGE_B;

        #pragma unroll
        for (int kk = 0; kk < 4; kk++) {
            const int k0 = kk * 16;
            uint32_t ahf[4][4], alf[4][4];
            #pragma unroll
            for (int mt = 0; mt < 4; mt++) {
                const uint32_t ra = stS + (wm * 64 + mt * 16 + arow) * ROWB
                                        + (k0 + acol) * 2;
                LDSM4(ahf[mt], ra);
                LDSM4(alf[mt], ra + OFF_AL);
            }
            uint32_t bf[8][2];
            #pragma unroll
            for (int np = 0; np < 4; np++) {
                const uint32_t rb = stS + OFF_B
                    + (wn * 64 + np * 16 + brow) * ROWB + (k0 + bcol) * 2;
                uint32_t r[4];
                LDSM4(r, rb);
                bf[2 * np][0]     = r[0]; bf[2 * np][1]     = r[1];
                bf[2 * np + 1][0] = r[2]; bf[2 * np + 1][1] = r[3];
            }
            #pragma unroll
            for (int mt = 0; mt < 4; mt++)
                #pragma unroll
                for (int nt = 0; nt < 8; nt++) {
                    float* a = acc[mt][nt];
                    mma_f16(a, ahf[mt], bf[nt]);
                    mma_f16(a, alf[mt], bf[nt]);
                }
        }
        __syncthreads();
    }

    // ---- epilogue ----
    const int g  = lane >> 2;
    const int t4 = lane & 3;
    if (mode == 0) {
        #pragma unroll
        for (int mt = 0; mt < 4; mt++) {
            const size_t r0 = rowBase + wm * 64 + mt * 16 + g;
            #pragma unroll
            for (int nt = 0; nt < 8; nt++) {
                const size_t cc = colBase + wn * 64 + nt * 8 + t4 * 2;
                const float b0 = bias[cc], b1 = bias[cc + 1];
                float2 v0, v1;
                v0.x = acc[mt][nt][0] + b0; v0.y = acc[mt][nt][1] + b1;
                v1.x = acc[mt][nt][2] + b0; v1.y = acc[mt][nt][3] + b1;
                *(float2*)&C[r0 * Nn + cc]       = v0;
                *(float2*)&C[(r0 + 8) * Nn + cc] = v1;
            }
        }
    } else {
        #pragma unroll
        for (int mt = 0; mt < 4; mt++) {
            const int tok0 = (int)rowBase + wm * 64 + mt * 16 + g;
            #pragma unroll
            for (int nt = 0; nt < 8; nt++) {
                const int cc = (int)colBase + wn * 64 + nt * 8 + t4 * 2;
                const int sec = cc >> 10;            // 0=q 1=k 2=v
                const int rest = cc & 1023;
                const int h = rest >> 6, d = rest & 63;
                float v00 = acc[mt][nt][0] + bias[cc];
                float v01 = acc[mt][nt][1] + bias[cc + 1];
                float v10 = acc[mt][nt][2] + bias[cc];
                float v11 = acc[mt][nt][3] + bias[cc + 1];
                __nv_bfloat16 *ph, *pl;
                if (sec == 0) {
                    ph = qh; pl = ql;
                    v00 *= QSCALE; v01 *= QSCALE; v10 *= QSCALE; v11 *= QSCALE;
                } else if (sec == 1) { ph = kh; pl = kl; }
                else                 { ph = vh; pl = vl; }
                const size_t o0 = (((size_t)((tok0 >> 11) * NH + h)) * SEQ
                                   + (tok0 & 2047)) * HD + d;
                const size_t o1 = o0 + 8 * HD;
                float h00 = bf16rt(v00), h01 = bf16rt(v01);
                float h10 = bf16rt(v10), h11 = bf16rt(v11);
                *(uint32_t*)&ph[o0] = pack_bf16x2(h00, h01);
                *(uint32_t*)&pl[o0] = pack_bf16x2(v00 - h00, v01 - h01);
                *(uint32_t*)&ph[o1] = pack_bf16x2(h10, h11);
                *(uint32_t*)&pl[o1] = pack_bf16x2(v10 - h10, v11 - h11);
            }
        }
    }
}

// ---------------- HMMA flash attention (bf16 3-term, validated) -----------
// Epilogue now writes fp16 hi/lo for the out-projection A side.
#define ATILE  (128 * ROWB)
#define ASTAGE (4 * ATILE)
#define MHA_SMEM (2 * ATILE + 2 * ASTAGE)   // 184320 B

__global__ __launch_bounds__(256, 1) void mha_mma(
    const __nv_bfloat16* __restrict__ qh, const __nv_bfloat16* __restrict__ ql,
    const __nv_bfloat16* __restrict__ kh, const __nv_bfloat16* __restrict__ kl,
    const __nv_bfloat16* __restrict__ vh, const __nv_bfloat16* __restrict__ vl,
    __half* __restrict__ ah, __half* __restrict__ al)
{
    extern __shared__ char smem[];
    const uint32_t sb = smem_u32(smem);
    const int tid  = threadIdx.x;
    const int wid  = tid >> 5;
    const int lane = tid & 31;

    const int qtile = blockIdx.x;
    const int bh    = blockIdx.y;
    const size_t base = (size_t)bh * SEQ * HD;

    const int lr = tid >> 3;
    const int lj = tid & 7;

    {
        const __nv_bfloat16* qsrc[2] = { qh + base, ql + base };
        #pragma unroll
        for (int it = 0; it < 8; it++) {
            const int t = it >> 2;
            const int r = lr + (it & 3) * 32;
            const uint32_t dst = sb + t * ATILE + r * ROWB + lj * 16;
            cp_async16(dst, qsrc[t] + (size_t)(qtile * 128 + r) * HD + lj * 8);
        }
        CP_COMMIT();
    }

    const __nv_bfloat16* kvsrc[4] = { kh + base, kl + base, vh + base, vl + base };
    auto load_kv = [&](int kb, int stage) {
        const uint32_t st = sb + 2 * ATILE + stage * ASTAGE;
        #pragma unroll
        for (int it = 0; it < 16; it++) {
            const int t = it >> 2;
            const int r = lr + (it & 3) * 32;
            const uint32_t dst = st + t * ATILE + r * ROWB + lj * 16;
            cp_async16(dst, kvsrc[t] + (size_t)(kb * 128 + r) * HD + lj * 8);
        }
        CP_COMMIT();
    };
    load_kv(0, 0);

    const int arow = ((lane >> 3) & 1) * 8 + (lane & 7);
    const int acol = ((lane >> 4) & 1) * 8;
    const int brow = ((lane >> 4) & 1) * 8 + (lane & 7);
    const int bcol = ((lane >> 3) & 1) * 8;
    const int vrow = ((lane >> 3) & 1) * 8 + (lane & 7);
    const int vcol = ((lane >> 4) & 1) * 8;

    CP_WAIT(1);
    __syncthreads();

    uint32_t qfh[4][4], qfl[4][4];
    #pragma unroll
    for (int kk = 0; kk < 4; kk++) {
        const uint32_t ra = sb + (wid * 16 + arow) * ROWB + (kk * 16 + acol) * 2;
        LDSM4(qfh[kk], ra);
        LDSM4(qfl[kk], ra + ATILE);
    }

    float oacc[8][4];
    #pragma unroll
    for (int i = 0; i < 8; i++)
        #pragma unroll
        for (int j = 0; j < 4; j++) oacc[i][j] = 0.f;
    float m0 = -1e30f, m1 = -1e30f, l0 = 0.f, l1 = 0.f;

    for (int kb = 0; kb < SEQ / 128; kb++) {
        const int s = kb & 1;
        if (kb + 1 < SEQ / 128) { load_kv(kb + 1, s ^ 1); CP_WAIT(1); }
        else                    { CP_WAIT(0); }
        __syncthreads();

        const uint32_t stK = sb + 2 * ATILE + s * ASTAGE;
        const uint32_t stV = stK + 2 * ATILE;

        float sacc[16][4];
        #pragma unroll
        for (int t = 0; t < 16; t++)
            #pragma unroll
            for (int j = 0; j < 4; j++) sacc[t][j] = 0.f;

        #pragma unroll
        for (int np = 0; np < 8; np++) {
            #pragma unroll
            for (int kk = 0; kk < 4; kk++) {
                const uint32_t rK = stK + (np * 16 + brow) * ROWB
                                        + (kk * 16 + bcol) * 2;
                uint32_t rh[4], rl[4];
                LDSM4(rh, rK);
                LDSM4(rl, rK + ATILE);
                mma_bf16(sacc[2 * np],     qfh[kk], &rh[0]);
                mma_bf16(sacc[2 * np],     qfl[kk], &rh[0]);
                mma_bf16(sacc[2 * np],     qfh[kk], &rl[0]);
                mma_bf16(sacc[2 * np + 1], qfh[kk], &rh[2]);
                mma_bf16(sacc[2 * np + 1], qfl[kk], &rh[2]);
                mma_bf16(sacc[2 * np + 1], qfh[kk], &rl[2]);
            }
        }

        float tm0 = -1e30f, tm1 = -1e30f;
        #pragma unroll
        for (int t = 0; t < 16; t++) {
            tm0 = fmaxf(tm0, fmaxf(sacc[t][0], sacc[t][1]));
            tm1 = fmaxf(tm1, fmaxf(sacc[t][2], sacc[t][3]));
        }
        tm0 = fmaxf(tm0, __shfl_xor_sync(0xFFFFFFFFu, tm0, 1));
        tm0 = fmaxf(tm0, __shfl_xor_sync(0xFFFFFFFFu, tm0, 2));
        tm1 = fmaxf(tm1, __shfl_xor_sync(0xFFFFFFFFu, tm1, 1));
        tm1 = fmaxf(tm1, __shfl_xor_sync(0xFFFFFFFFu, tm1, 2));

        const float nm0 = fmaxf(m0, tm0);
        const float nm1 = fmaxf(m1, tm1);
        const float a0 = ex2f(m0 - nm0);
        const float a1 = ex2f(m1 - nm1);
        m0 = nm0; m1 = nm1;

        float rs0 = 0.f, rs1 = 0.f;
        #pragma unroll
        for (int t = 0; t < 16; t++) {
            sacc[t][0] = ex2f(sacc[t][0] - nm0);
            sacc[t][1] = ex2f(sacc[t][1] - nm0);
            sacc[t][2] = ex2f(sacc[t][2] - nm1);
            sacc[t][3] = ex2f(sacc[t][3] - nm1);
            rs0 += sacc[t][0] + sacc[t][1];
            rs1 += sacc[t][2] + sacc[t][3];
        }
        rs0 += __shfl_xor_sync(0xFFFFFFFFu, rs0, 1);
        rs0 += __shfl_xor_sync(0xFFFFFFFFu, rs0, 2);
        rs1 += __shfl_xor_sync(0xFFFFFFFFu, rs1, 1);
        rs1 += __shfl_xor_sync(0xFFFFFFFFu, rs1, 2);
        l0 = l0 * a0 + rs0;
        l1 = l1 * a1 + rs1;

        #pragma unroll
        for (int nt = 0; nt < 8; nt++) {
            oacc[nt][0] *= a0; oacc[nt][1] *= a0;
            oacc[nt][2] *= a1; oacc[nt][3] *= a1;
        }

        #pragma unroll
        for (int kc = 0; kc < 8; kc++) {
            const int t0 = 2 * kc, t1 = 2 * kc + 1;
            uint32_t pah[4], pal[4];
            {
                float h00 = bf16rt(sacc[t0][0]), h01 = bf16rt(sacc[t0][1]);
                float h02 = bf16rt(sacc[t0][2]), h03 = bf16rt(sacc[t0][3]);
                float h10 = bf16rt(sacc[t1][0]), h11 = bf16rt(sacc[t1][1]);
                float h12 = bf16rt(sacc[t1][2]), h13 = bf16rt(sacc[t1][3]);
                pah[0] = pack_bf16x2(h00, h01);
                pah[1] = pack_bf16x2(h02, h03);
                pah[2] = pack_bf16x2(h10, h11);
                pah[3] = pack_bf16x2(h12, h13);
                pal[0] = pack_bf16x2(sacc[t0][0] - h00, sacc[t0][1] - h01);
                pal[1] = pack_bf16x2(sacc[t0][2] - h02, sacc[t0][3] - h03);
                pal[2] = pack_bf16x2(sacc[t1][0] - h10, sacc[t1][1] - h11);
                pal[3] = pack_bf16x2(sacc[t1][2] - h12, sacc[t1][3] - h13);
            }
            #pragma unroll
            for (int nv = 0; nv < 4; nv++) {
                const uint32_t rV = stV + (kc * 16 + vrow) * ROWB
                                        + (nv * 16 + vcol) * 2;
                uint32_t vh_[4], vl_[4];
                LDSM4T(vh_, rV);
                LDSM4T(vl_, rV + ATILE);
                mma_bf16(oacc[2 * nv],     pah, &vh_[0]);
                mma_bf16(oacc[2 * nv],     pal, &vh_[0]);
                mma_bf16(oacc[2 * nv],     pah, &vl_[0]);
                mma_bf16(oacc[2 * nv + 1], pah, &vh_[2]);
                mma_bf16(oacc[2 * nv + 1], pal, &vh_[2]);
                mma_bf16(oacc[2 * nv + 1], pah, &vl_[2]);
            }
        }
        __syncthreads();
    }

    // ---- epilogue: normalize, fp16 hi/lo split, write to g_ah / g_al ----
    const int g  = lane >> 2;
    const int t4 = lane & 3;
    const float inv0 = 1.f / l0;
    const float inv1 = 1.f / l1;
    const int b = bh >> 4, h = bh & 15;
    const size_t tok0 = (size_t)b * SEQ + qtile * 128 + wid * 16 + g;
    const int colb = h * HD;
    #pragma unroll
    for (int nt = 0; nt < 8; nt++) {
        const int cc = colb + nt * 8 + 2 * t4;
        float x0 = oacc[nt][0] * inv0, x1 = oacc[nt][1] * inv0;
        float y0 = oacc[nt][2] * inv1, y1 = oacc[nt][3] * inv1;
        float hx0 = f16rt(x0), hx1 = f16rt(x1);
        float hy0 = f16rt(y0), hy1 = f16rt(y1);
        *(uint32_t*)&ah[tok0 * EMB + cc]       = pack_f16x2(hx0, hx1);
        *(uint32_t*)&al[tok0 * EMB + cc]       = pack_f16x2(x0 - hx0, x1 - hx1);
        *(uint32_t*)&ah[(tok0 + 8) * EMB + cc] = pack_f16x2(hy0, hy1);
        *(uint32_t*)&al[(tok0 + 8) * EMB + cc] = pack_f16x2(y0 - hy0, y1 - hy1);
    }
}

// ---------------------------------------------------------------------------
extern "C" void kernel_launch(void* const* d_in, const int* in_sizes, int n_in,
                              void* d_out, int out_size)
{
    const float* x     = (const float*)d_in[0];
    const float* w_in  = (const float*)d_in[1];
    const float* b_in  = (const float*)d_in[2];
    const float* w_out = (const float*)d_in[3];
    const float* b_out = (const float*)d_in[4];
    float* out = (float*)d_out;

    __half *xh, *xl, *wih, *woh, *ah, *al;
    __nv_bfloat16 *qh, *ql, *kh, *kl, *vh, *vl;
    cudaGetSymbolAddress((void**)&xh,  g_xh);
    cudaGetSymbolAddress((void**)&xl,  g_xl);
    cudaGetSymbolAddress((void**)&wih, g_wih);
    cudaGetSymbolAddress((void**)&woh, g_woh);
    cudaGetSymbolAddress((void**)&ah,  g_ah);
    cudaGetSymbolAddress((void**)&al,  g_al);
    cudaGetSymbolAddress((void**)&qh,  g_qh);
    cudaGetSymbolAddress((void**)&ql,  g_ql);
    cudaGetSymbolAddress((void**)&kh,  g_kh);
    cudaGetSymbolAddress((void**)&kl,  g_kl);
    cudaGetSymbolAddress((void**)&vh,  g_vh);
    cudaGetSymbolAddress((void**)&vl,  g_vl);

    cudaFuncSetAttribute(mma_gemm,
                         cudaFuncAttributeMaxDynamicSharedMemorySize, GEMM_SMEM);
    cudaFuncSetAttribute(mha_mma,
                         cudaFuncAttributeMaxDynamicSharedMemorySize, MHA_SMEM);

    // 0) all fp32 -> fp16 conversions in one launch
    prep<<<(NPREP + 255) / 256, 256>>>(x, w_in, w_out, xh, xl, wih, woh);

    // 1) QKV projection (fp16, A-split), fused epilogue -> bf16 q/k/v hi/lo
    mma_gemm<<<dim3(E3 / 256, TOK / 128), 256, GEMM_SMEM>>>(
        xh, xl, wih, b_in, nullptr,
        qh, ql, kh, kl, vh, vl, E3, EMB, 1);

    // 2) HMMA flash attention (bf16 3-term) -> fp16 hi/lo ah/al
    mha_mma<<<dim3(SEQ / 128, 2 * NH), 256, MHA_SMEM>>>(
        qh, ql, kh, kl, vh, vl, ah, al);

    // 3) out-projection (fp16, A-split), fp32 out + bias; 128 CTAs = 1 wave
    mma_gemm<<<dim3(EMB / 256, TOK / 128), 256, GEMM_SMEM>>>(
        ah, al, woh, b_out, out,
        nullptr, nullptr, nullptr, nullptr, nullptr, nullptr, EMB, EMB, 0);
}

// round 12
// speedup vs baseline: 5.3347x; 1.3671x over previous
#include <cuda_runtime.h>
#include <cuda_bf16.h>
#include <cuda_fp16.h>
#include <cstdint>

#define TOK 4096
#define SEQ 2048
#define EMB 1024
#define E3  3072
#define NH  16
#define HD  64

// ---------------- scratch (cudaMalloc forbidden) ----------------
__device__ __half g_xh[(size_t)TOK * EMB], g_xl[(size_t)TOK * EMB];
__device__ __half g_wih[(size_t)E3 * EMB];          // w_in, single fp16
__device__ __half g_woh[(size_t)EMB * EMB];         // w_out, single fp16
__device__ __half g_ah[(size_t)TOK * EMB], g_al[(size_t)TOK * EMB];
// per-(b,h) contiguous: Q split hi/lo, K and V single fp16: [B*NH][SEQ][HD]
__device__ __half g_qh[(size_t)TOK * EMB], g_ql[(size_t)TOK * EMB];
__device__ __half g_kf[(size_t)TOK * EMB];
__device__ __half g_vf[(size_t)TOK * EMB];

// ---------------- helpers ----------------
__device__ __forceinline__ uint32_t smem_u32(const void* p) {
    uint32_t a;
    asm("{ .reg .u64 t; cvta.to.shared.u64 t, %1; cvt.u32.u64 %0, t; }"
        : "=r"(a) : "l"(p));
    return a;
}
__device__ __forceinline__ void cp_async16(uint32_t dst, const void* src) {
    asm volatile("cp.async.cg.shared.global [%0], [%1], 16;"
                 :: "r"(dst), "l"(src));
}
#define CP_COMMIT()  asm volatile("cp.async.commit_group;" ::: "memory")
#define CP_WAIT(n)   asm volatile("cp.async.wait_group %0;" :: "n"(n) : "memory")

#define LDSM4(r, a)                                                         \
    asm volatile("ldmatrix.sync.aligned.m8n8.x4.shared.b16 "                \
                 "{%0,%1,%2,%3}, [%4];"                                     \
                 : "=r"((r)[0]), "=r"((r)[1]), "=r"((r)[2]), "=r"((r)[3])   \
                 : "r"(a))
#define LDSM4T(r, a)                                                        \
    asm volatile("ldmatrix.sync.aligned.m8n8.x4.trans.shared.b16 "          \
                 "{%0,%1,%2,%3}, [%4];"                                     \
                 : "=r"((r)[0]), "=r"((r)[1]), "=r"((r)[2]), "=r"((r)[3])   \
                 : "r"(a))

__device__ __forceinline__ void mma_f16(float* d, const uint32_t* a,
                                        const uint32_t* b) {
    asm volatile(
        "mma.sync.aligned.m16n8k16.row.col.f32.f16.f16.f32 "
        "{%0,%1,%2,%3}, {%4,%5,%6,%7}, {%8,%9}, {%0,%1,%2,%3};"
        : "+f"(d[0]), "+f"(d[1]), "+f"(d[2]), "+f"(d[3])
        : "r"(a[0]), "r"(a[1]), "r"(a[2]), "r"(a[3]), "r"(b[0]), "r"(b[1]));
}
__device__ __forceinline__ float ex2f(float x) {
    float y; asm("ex2.approx.ftz.f32 %0, %1;" : "=f"(y) : "f"(x)); return y;
}
__device__ __forceinline__ uint32_t pack_f16x2(float lo, float hi) {
    __half2 h = __floats2half2_rn(lo, hi);
    return *(uint32_t*)&h;
}
__device__ __forceinline__ float f16rt(float x) {
    return __half2float(__float2half_rn(x));
}

// ---------------- single prep kernel: all fp32 -> fp16 conversions --------
#define NX4  (TOK * EMB / 4)
#define NW14 (E3 * EMB / 4)
#define NW24 (EMB * EMB / 4)
#define NPREP (NX4 + NW14 + NW24)

__global__ __launch_bounds__(256) void prep(
    const float* __restrict__ x, const float* __restrict__ w_in,
    const float* __restrict__ w_out,
    __half* __restrict__ xh, __half* __restrict__ xl,
    __half* __restrict__ wih, __half* __restrict__ woh)
{
    int i = blockIdx.x * blockDim.x + threadIdx.x;
    if (i < NX4) {
        float4 v = ((const float4*)x)[i];
        float hx = f16rt(v.x), hy = f16rt(v.y), hz = f16rt(v.z), hw = f16rt(v.w);
        *(uint32_t*)&xh[4 * (size_t)i]     = pack_f16x2(hx, hy);
        *(uint32_t*)&xh[4 * (size_t)i + 2] = pack_f16x2(hz, hw);
        *(uint32_t*)&xl[4 * (size_t)i]     = pack_f16x2(v.x - hx, v.y - hy);
        *(uint32_t*)&xl[4 * (size_t)i + 2] = pack_f16x2(v.z - hz, v.w - hw);
    } else if (i < NX4 + NW14) {
        const int j = i - NX4;
        float4 v = ((const float4*)w_in)[j];
        *(uint32_t*)&wih[4 * (size_t)j]     = pack_f16x2(v.x, v.y);
        *(uint32_t*)&wih[4 * (size_t)j + 2] = pack_f16x2(v.z, v.w);
    } else if (i < NPREP) {
        const int j = i - NX4 - NW14;
        float4 v = ((const float4*)w_out)[j];
        *(uint32_t*)&woh[4 * (size_t)j]     = pack_f16x2(v.x, v.y);
        *(uint32_t*)&woh[4 * (size_t)j + 2] = pack_f16x2(v.z, v.w);
    }
}

// ---------------- fp16 GEMM: C = (Ah+Al) @ B^T (+bias) -------------------
// mode 0: fp32 C + bias.  mode 1: QKV epilogue -> q fp16 hi/lo (pre-scaled),
// k/v single fp16, per-(b,h) layout.
#define QSCALE 0.18033688011112042f
#define KC     64
#define ROWB   144
#define OFF_AL (128 * ROWB)
#define OFF_B  (2 * 128 * ROWB)
#define STAGE_B (OFF_B + 256 * ROWB)
#define GEMM_SMEM (2 * STAGE_B)              // 147456

__global__ __launch_bounds__(256, 1) void mma_gemm(
    const __half* __restrict__ Ah, const __half* __restrict__ Al,
    const __half* __restrict__ B,
    const float* __restrict__ bias, float* __restrict__ C,
    __half* __restrict__ qh, __half* __restrict__ ql,
    __half* __restrict__ kf, __half* __restrict__ vf,
    int Nn, int K, int mode)
{
    extern __shared__ char smem[];
    const uint32_t sb = smem_u32(smem);
    const int tid  = threadIdx.x;
    const int wid  = tid >> 5;
    const int lane = tid & 31;
    const int wm = wid >> 2;
    const int wn = wid & 3;

    const size_t rowBase = (size_t)blockIdx.y * 128;
    const size_t colBase = (size_t)blockIdx.x * 256;

    const __half* sAh = Ah + rowBase * K;
    const __half* sAl = Al + rowBase * K;
    const __half* sB  = B  + colBase * K;

    const int r0l = tid >> 3;
    const int lj  = tid & 7;
    auto load_chunk = [&](int c, int stage) {
        const uint32_t st = sb + stage * STAGE_B;
        const int kof = c * KC + lj * 8;
        #pragma unroll
        for (int it = 0; it < 16; it++) {
            const int r = it * 32 + r0l;
            uint32_t dst; const __half* src;
            if (it < 4)      { dst = st + r * ROWB + lj * 16;
                               src = sAh + (size_t)r * K + kof; }
            else if (it < 8) { const int rr = r - 128;
                               dst = st + OFF_AL + rr * ROWB + lj * 16;
                               src = sAl + (size_t)rr * K + kof; }
            else             { const int rr = r - 256;
                               dst = st + OFF_B + rr * ROWB + lj * 16;
                               src = sB + (size_t)rr * K + kof; }
            cp_async16(dst, src);
        }
        CP_COMMIT();
    };

    float acc[4][8][4];
    #pragma unroll
    for (int i = 0; i < 4; i++)
        #pragma unroll
        for (int j = 0; j < 8; j++)
            #pragma unroll
            for (int k = 0; k < 4; k++) acc[i][j][k] = 0.f;

    const int arow = ((lane >> 3) & 1) * 8 + (lane & 7);
    const int acol = ((lane >> 4) & 1) * 8;
    const int brow = ((lane >> 4) & 1) * 8 + (lane & 7);
    const int bcol = ((lane >> 3) & 1) * 8;

    const int nch = K / KC;
    load_chunk(0, 0);

    for (int c = 0; c < nch; c++) {
        const int s = c & 1;
        if (c + 1 < nch) { load_chunk(c + 1, s ^ 1); CP_WAIT(1); }
        else             { CP_WAIT(0); }
        __syncthreads();

        const uint32_t stS = sb + s * STAGE_B;

        #pragma unroll
        for (int kk = 0; kk < 4; kk++) {
            const int k0 = kk * 16;
            uint32_t ahf[4][4], alf[4][4];
            #pragma unroll
            for (int mt = 0; mt < 4; mt++) {
                const uint32_t ra = stS + (wm * 64 + mt * 16 + arow) * ROWB
                                        + (k0 + acol) * 2;
                LDSM4(ahf[mt], ra);
                LDSM4(alf[mt], ra + OFF_AL);
            }
            uint32_t bf[8][2];
            #pragma unroll
            for (int np = 0; np < 4; np++) {
                const uint32_t rb = stS + OFF_B
                    + (wn * 64 + np * 16 + brow) * ROWB + (k0 + bcol) * 2;
                uint32_t r[4];
                LDSM4(r, rb);
                bf[2 * np][0]     = r[0]; bf[2 * np][1]     = r[1];
                bf[2 * np + 1][0] = r[2]; bf[2 * np + 1][1] = r[3];
            }
            #pragma unroll
            for (int mt = 0; mt < 4; mt++)
                #pragma unroll
                for (int nt = 0; nt < 8; nt++) {
                    float* a = acc[mt][nt];
                    mma_f16(a, ahf[mt], bf[nt]);
                    mma_f16(a, alf[mt], bf[nt]);
                }
        }
        __syncthreads();
    }

    // ---- epilogue ----
    const int g  = lane >> 2;
    const int t4 = lane & 3;
    if (mode == 0) {
        #pragma unroll
        for (int mt = 0; mt < 4; mt++) {
            const size_t r0 = rowBase + wm * 64 + mt * 16 + g;
            #pragma unroll
            for (int nt = 0; nt < 8; nt++) {
                const size_t cc = colBase + wn * 64 + nt * 8 + t4 * 2;
                const float b0 = bias[cc], b1 = bias[cc + 1];
                float2 v0, v1;
                v0.x = acc[mt][nt][0] + b0; v0.y = acc[mt][nt][1] + b1;
                v1.x = acc[mt][nt][2] + b0; v1.y = acc[mt][nt][3] + b1;
                *(float2*)&C[r0 * Nn + cc]       = v0;
                *(float2*)&C[(r0 + 8) * Nn + cc] = v1;
            }
        }
    } else {
        #pragma unroll
        for (int mt = 0; mt < 4; mt++) {
            const int tok0 = (int)rowBase + wm * 64 + mt * 16 + g;
            #pragma unroll
            for (int nt = 0; nt < 8; nt++) {
                const int cc = (int)colBase + wn * 64 + nt * 8 + t4 * 2;
                const int sec = cc >> 10;            // 0=q 1=k 2=v
                const int rest = cc & 1023;
                const int h = rest >> 6, d = rest & 63;
                float v00 = acc[mt][nt][0] + bias[cc];
                float v01 = acc[mt][nt][1] + bias[cc + 1];
                float v10 = acc[mt][nt][2] + bias[cc];
                float v11 = acc[mt][nt][3] + bias[cc + 1];
                const size_t o0 = (((size_t)((tok0 >> 11) * NH + h)) * SEQ
                                   + (tok0 & 2047)) * HD + d;
                const size_t o1 = o0 + 8 * HD;
                if (sec == 0) {
                    v00 *= QSCALE; v01 *= QSCALE; v10 *= QSCALE; v11 *= QSCALE;
                    float h00 = f16rt(v00), h01 = f16rt(v01);
                    float h10 = f16rt(v10), h11 = f16rt(v11);
                    *(uint32_t*)&qh[o0] = pack_f16x2(h00, h01);
                    *(uint32_t*)&ql[o0] = pack_f16x2(v00 - h00, v01 - h01);
                    *(uint32_t*)&qh[o1] = pack_f16x2(h10, h11);
                    *(uint32_t*)&ql[o1] = pack_f16x2(v10 - h10, v11 - h11);
                } else {
                    __half* p = (sec == 1) ? kf : vf;
                    *(uint32_t*)&p[o0] = pack_f16x2(v00, v01);
                    *(uint32_t*)&p[o1] = pack_f16x2(v10, v11);
                }
            }
        }
    }
}

// ---------------- fp16 flash attention -----------------------------------
// QK^T = Qh*K + Ql*K (Q split, K single).  PV = P*V (single/single).
// CTA: 128 q x (b,h); 8 warps x 16 q-rows, full 128-key width per warp.
#define ATILE  (128 * ROWB)          // 18432
#define ASTAGE (2 * ATILE)           // K, V single
#define MHA_SMEM (2 * ATILE + 2 * ASTAGE)   // 110592 B

__global__ __launch_bounds__(256, 1) void mha_mma(
    const __half* __restrict__ qh, const __half* __restrict__ ql,
    const __half* __restrict__ kf, const __half* __restrict__ vf,
    __half* __restrict__ ah, __half* __restrict__ al)
{
    extern __shared__ char smem[];
    const uint32_t sb = smem_u32(smem);
    const int tid  = threadIdx.x;
    const int wid  = tid >> 5;
    const int lane = tid & 31;

    const int qtile = blockIdx.x;
    const int bh    = blockIdx.y;
    const size_t base = (size_t)bh * SEQ * HD;

    const int lr = tid >> 3;
    const int lj = tid & 7;

    // Q hi/lo tiles
    {
        const __half* qsrc[2] = { qh + base, ql + base };
        #pragma unroll
        for (int it = 0; it < 8; it++) {
            const int t = it >> 2;
            const int r = lr + (it & 3) * 32;
            const uint32_t dst = sb + t * ATILE + r * ROWB + lj * 16;
            cp_async16(dst, qsrc[t] + (size_t)(qtile * 128 + r) * HD + lj * 8);
        }
        CP_COMMIT();
    }

    const __half* kvsrc[2] = { kf + base, vf + base };
    auto load_kv = [&](int kb, int stage) {
        const uint32_t st = sb + 2 * ATILE + stage * ASTAGE;
        #pragma unroll
        for (int it = 0; it < 8; it++) {
            const int t = it >> 2;
            const int r = lr + (it & 3) * 32;
            const uint32_t dst = st + t * ATILE + r * ROWB + lj * 16;
            cp_async16(dst, kvsrc[t] + (size_t)(kb * 128 + r) * HD + lj * 8);
        }
        CP_COMMIT();
    };
    load_kv(0, 0);

    const int arow = ((lane >> 3) & 1) * 8 + (lane & 7);
    const int acol = ((lane >> 4) & 1) * 8;
    const int brow = ((lane >> 4) & 1) * 8 + (lane & 7);
    const int bcol = ((lane >> 3) & 1) * 8;
    const int vrow = ((lane >> 3) & 1) * 8 + (lane & 7);
    const int vcol = ((lane >> 4) & 1) * 8;

    CP_WAIT(1);
    __syncthreads();

    uint32_t qfh[4][4], qfl[4][4];
    #pragma unroll
    for (int kk = 0; kk < 4; kk++) {
        const uint32_t ra = sb + (wid * 16 + arow) * ROWB + (kk * 16 + acol) * 2;
        LDSM4(qfh[kk], ra);
        LDSM4(qfl[kk], ra + ATILE);
    }

    float oacc[8][4];
    #pragma unroll
    for (int i = 0; i < 8; i++)
        #pragma unroll
        for (int j = 0; j < 4; j++) oacc[i][j] = 0.f;
    float m0 = -1e30f, m1 = -1e30f, l0 = 0.f, l1 = 0.f;

    for (int kb = 0; kb < SEQ / 128; kb++) {
        const int s = kb & 1;
        if (kb + 1 < SEQ / 128) { load_kv(kb + 1, s ^ 1); CP_WAIT(1); }
        else                    { CP_WAIT(0); }
        __syncthreads();

        const uint32_t stK = sb + 2 * ATILE + s * ASTAGE;
        const uint32_t stV = stK + ATILE;

        // ---- S = (Qh + Ql) K^T ----
        float sacc[16][4];
        #pragma unroll
        for (int t = 0; t < 16; t++)
            #pragma unroll
            for (int j = 0; j < 4; j++) sacc[t][j] = 0.f;

        #pragma unroll
        for (int np = 0; np < 8; np++) {
            #pragma unroll
            for (int kk = 0; kk < 4; kk++) {
                const uint32_t rK = stK + (np * 16 + brow) * ROWB
                                        + (kk * 16 + bcol) * 2;
                uint32_t rk[4];
                LDSM4(rk, rK);
                mma_f16(sacc[2 * np],     qfh[kk], &rk[0]);
                mma_f16(sacc[2 * np],     qfl[kk], &rk[0]);
                mma_f16(sacc[2 * np + 1], qfh[kk], &rk[2]);
                mma_f16(sacc[2 * np + 1], qfl[kk], &rk[2]);
            }
        }

        // ---- online softmax (base-2) ----
        float tm0 = -1e30f, tm1 = -1e30f;
        #pragma unroll
        for (int t = 0; t < 16; t++) {
            tm0 = fmaxf(tm0, fmaxf(sacc[t][0], sacc[t][1]));
            tm1 = fmaxf(tm1, fmaxf(sacc[t][2], sacc[t][3]));
        }
        tm0 = fmaxf(tm0, __shfl_xor_sync(0xFFFFFFFFu, tm0, 1));
        tm0 = fmaxf(tm0, __shfl_xor_sync(0xFFFFFFFFu, tm0, 2));
        tm1 = fmaxf(tm1, __shfl_xor_sync(0xFFFFFFFFu, tm1, 1));
        tm1 = fmaxf(tm1, __shfl_xor_sync(0xFFFFFFFFu, tm1, 2));

        const float nm0 = fmaxf(m0, tm0);
        const float nm1 = fmaxf(m1, tm1);
        const float a0 = ex2f(m0 - nm0);
        const float a1 = ex2f(m1 - nm1);
        m0 = nm0; m1 = nm1;

        float rs0 = 0.f, rs1 = 0.f;
        #pragma unroll
        for (int t = 0; t < 16; t++) {
            sacc[t][0] = ex2f(sacc[t][0] - nm0);
            sacc[t][1] = ex2f(sacc[t][1] - nm0);
            sacc[t][2] = ex2f(sacc[t][2] - nm1);
            sacc[t][3] = ex2f(sacc[t][3] - nm1);
            rs0 += sacc[t][0] + sacc[t][1];
            rs1 += sacc[t][2] + sacc[t][3];
        }
        rs0 += __shfl_xor_sync(0xFFFFFFFFu, rs0, 1);
        rs0 += __shfl_xor_sync(0xFFFFFFFFu, rs0, 2);
        rs1 += __shfl_xor_sync(0xFFFFFFFFu, rs1, 1);
        rs1 += __shfl_xor_sync(0xFFFFFFFFu, rs1, 2);
        l0 = l0 * a0 + rs0;
        l1 = l1 * a1 + rs1;

        #pragma unroll
        for (int nt = 0; nt < 8; nt++) {
            oacc[nt][0] *= a0; oacc[nt][1] *= a0;
            oacc[nt][2] *= a1; oacc[nt][3] *= a1;
        }

        // ---- O += P V (single fp16 P and V) ----
        #pragma unroll
        for (int kc = 0; kc < 8; kc++) {
            const int t0 = 2 * kc, t1 = 2 * kc + 1;
            uint32_t pa[4];
            pa[0] = pack_f16x2(sacc[t0][0], sacc[t0][1]);
            pa[1] = pack_f16x2(sacc[t0][2], sacc[t0][3]);
            pa[2] = pack_f16x2(sacc[t1][0], sacc[t1][1]);
            pa[3] = pack_f16x2(sacc[t1][2], sacc[t1][3]);
            #pragma unroll
            for (int nv = 0; nv < 4; nv++) {
                const uint32_t rV = stV + (kc * 16 + vrow) * ROWB
                                        + (nv * 16 + vcol) * 2;
                uint32_t vv[4];
                LDSM4T(vv, rV);
                mma_f16(oacc[2 * nv],     pa, &vv[0]);
                mma_f16(oacc[2 * nv + 1], pa, &vv[2]);
            }
        }
        __syncthreads();
    }

    // ---- epilogue: normalize, fp16 hi/lo split, write to g_ah / g_al ----
    const int g  = lane >> 2;
    const int t4 = lane & 3;
    const float inv0 = 1.f / l0;
    const float inv1 = 1.f / l1;
    const int b = bh >> 4, h = bh & 15;
    const size_t tok0 = (size_t)b * SEQ + qtile * 128 + wid * 16 + g;
    const int colb = h * HD;
    #pragma unroll
    for (int nt = 0; nt < 8; nt++) {
        const int cc = colb + nt * 8 + 2 * t4;
        float x0 = oacc[nt][0] * inv0, x1 = oacc[nt][1] * inv0;
        float y0 = oacc[nt][2] * inv1, y1 = oacc[nt][3] * inv1;
        float hx0 = f16rt(x0), hx1 = f16rt(x1);
        float hy0 = f16rt(y0), hy1 = f16rt(y1);
        *(uint32_t*)&ah[tok0 * EMB + cc]       = pack_f16x2(hx0, hx1);
        *(uint32_t*)&al[tok0 * EMB + cc]       = pack_f16x2(x0 - hx0, x1 - hx1);
        *(uint32_t*)&ah[(tok0 + 8) * EMB + cc] = pack_f16x2(hy0, hy1);
        *(uint32_t*)&al[(tok0 + 8) * EMB + cc] = pack_f16x2(y0 - hy0, y1 - hy1);
    }
}

// ---------------------------------------------------------------------------
extern "C" void kernel_launch(void* const* d_in, const int* in_sizes, int n_in,
                              void* d_out, int out_size)
{
    const float* x     = (const float*)d_in[0];
    const float* w_in  = (const float*)d_in[1];
    const float* b_in  = (const float*)d_in[2];
    const float* w_out = (const float*)d_in[3];
    const float* b_out = (const float*)d_in[4];
    float* out = (float*)d_out;

    __half *xh, *xl, *wih, *woh, *ah, *al, *qh, *ql, *kf, *vf;
    cudaGetSymbolAddress((void**)&xh,  g_xh);
    cudaGetSymbolAddress((void**)&xl,  g_xl);
    cudaGetSymbolAddress((void**)&wih, g_wih);
    cudaGetSymbolAddress((void**)&woh, g_woh);
    cudaGetSymbolAddress((void**)&ah,  g_ah);
    cudaGetSymbolAddress((void**)&al,  g_al);
    cudaGetSymbolAddress((void**)&qh,  g_qh);
    cudaGetSymbolAddress((void**)&ql,  g_ql);
    cudaGetSymbolAddress((void**)&kf,  g_kf);
    cudaGetSymbolAddress((void**)&vf,  g_vf);

    cudaFuncSetAttribute(mma_gemm,
                         cudaFuncAttributeMaxDynamicSharedMemorySize, GEMM_SMEM);
    cudaFuncSetAttribute(mha_mma,
                         cudaFuncAttributeMaxDynamicSharedMemorySize, MHA_SMEM);

    // 0) all fp32 -> fp16 conversions in one launch
    prep<<<(NPREP + 255) / 256, 256>>>(x, w_in, w_out, xh, xl, wih, woh);

    // 1) QKV projection (fp16, A-split), fused epilogue -> q hi/lo, k/v single
    mma_gemm<<<dim3(E3 / 256, TOK / 128), 256, GEMM_SMEM>>>(
        xh, xl, wih, b_in, nullptr, qh, ql, kf, vf, E3, EMB, 1);

    // 2) fp16 flash attention -> fp16 hi/lo ah/al
    mha_mma<<<dim3(SEQ / 128, 2 * NH), 256, MHA_SMEM>>>(
        qh, ql, kf, vf, ah, al);

    // 3) out-projection (fp16, A-split), fp32 out + bias
    mma_gemm<<<dim3(EMB / 256, TOK / 128), 256, GEMM_SMEM>>>(
        ah, al, woh, b_out, out,
        nullptr, nullptr, nullptr, nullptr, EMB, EMB, 0);
}

// round 14
// speedup vs baseline: 6.7919x; 1.2732x over previous
#include <cuda_runtime.h>
#include <cuda_bf16.h>
#include <cuda_fp16.h>
#include <cstdint>

#define TOK 4096
#define SEQ 2048
#define EMB 1024
#define E3  3072
#define NH  16
#define HD  64

// ---------------- scratch (cudaMalloc forbidden) ----------------
__device__ __half g_xh[(size_t)TOK * EMB];          // x, single fp16
__device__ __half g_wih[(size_t)E3 * EMB];          // w_in, single fp16
__device__ __half g_woh[(size_t)EMB * EMB];         // w_out, single fp16
__device__ __half g_af[(size_t)TOK * EMB];          // attention out, single fp16
// per-(b,h) contiguous: Q split hi/lo, K and V single fp16: [B*NH][SEQ][HD]
__device__ __half g_qh[(size_t)TOK * EMB], g_ql[(size_t)TOK * EMB];
__device__ __half g_kf[(size_t)TOK * EMB];
__device__ __half g_vf[(size_t)TOK * EMB];

// ---------------- helpers ----------------
__device__ __forceinline__ uint32_t smem_u32(const void* p) {
    uint32_t a;
    asm("{ .reg .u64 t; cvta.to.shared.u64 t, %1; cvt.u32.u64 %0, t; }"
        : "=r"(a) : "l"(p));
    return a;
}
__device__ __forceinline__ void cp_async16(uint32_t dst, const void* src) {
    asm volatile("cp.async.cg.shared.global [%0], [%1], 16;"
                 :: "r"(dst), "l"(src));
}
#define CP_COMMIT()  asm volatile("cp.async.commit_group;" ::: "memory")
#define CP_WAIT(n)   asm volatile("cp.async.wait_group %0;" :: "n"(n) : "memory")

#define LDSM4(r, a)                                                         \
    asm volatile("ldmatrix.sync.aligned.m8n8.x4.shared.b16 "                \
                 "{%0,%1,%2,%3}, [%4];"                                     \
                 : "=r"((r)[0]), "=r"((r)[1]), "=r"((r)[2]), "=r"((r)[3])   \
                 : "r"(a))
#define LDSM4T(r, a)                                                        \
    asm volatile("ldmatrix.sync.aligned.m8n8.x4.trans.shared.b16 "          \
                 "{%0,%1,%2,%3}, [%4];"                                     \
                 : "=r"((r)[0]), "=r"((r)[1]), "=r"((r)[2]), "=r"((r)[3])   \
                 : "r"(a))

__device__ __forceinline__ void mma_f16(float* d, const uint32_t* a,
                                        const uint32_t* b) {
    asm volatile(
        "mma.sync.aligned.m16n8k16.row.col.f32.f16.f16.f32 "
        "{%0,%1,%2,%3}, {%4,%5,%6,%7}, {%8,%9}, {%0,%1,%2,%3};"
        : "+f"(d[0]), "+f"(d[1]), "+f"(d[2]), "+f"(d[3])
        : "r"(a[0]), "r"(a[1]), "r"(a[2]), "r"(a[3]), "r"(b[0]), "r"(b[1]));
}
__device__ __forceinline__ float ex2f(float x) {
    float y; asm("ex2.approx.ftz.f32 %0, %1;" : "=f"(y) : "f"(x)); return y;
}
__device__ __forceinline__ uint32_t pack_f16x2(float lo, float hi) {
    __half2 h = __floats2half2_rn(lo, hi);
    return *(uint32_t*)&h;
}
__device__ __forceinline__ float f16rt(float x) {
    return __half2float(__float2half_rn(x));
}

// ---------------- single prep kernel: fp32 -> fp16 conversions -----------
#define NX4  (TOK * EMB / 4)
#define NW14 (E3 * EMB / 4)
#define NW24 (EMB * EMB / 4)
#define NPREP (NX4 + NW14 + NW24)

__global__ __launch_bounds__(256) void prep(
    const float* __restrict__ x, const float* __restrict__ w_in,
    const float* __restrict__ w_out,
    __half* __restrict__ xh, __half* __restrict__ wih,
    __half* __restrict__ woh)
{
    int i = blockIdx.x * blockDim.x + threadIdx.x;
    if (i < NX4) {
        float4 v = ((const float4*)x)[i];
        *(uint32_t*)&xh[4 * (size_t)i]     = pack_f16x2(v.x, v.y);
        *(uint32_t*)&xh[4 * (size_t)i + 2] = pack_f16x2(v.z, v.w);
    } else if (i < NX4 + NW14) {
        const int j = i - NX4;
        float4 v = ((const float4*)w_in)[j];
        *(uint32_t*)&wih[4 * (size_t)j]     = pack_f16x2(v.x, v.y);
        *(uint32_t*)&wih[4 * (size_t)j + 2] = pack_f16x2(v.z, v.w);
    } else if (i < NPREP) {
        const int j = i - NX4 - NW14;
        float4 v = ((const float4*)w_out)[j];
        *(uint32_t*)&woh[4 * (size_t)j]     = pack_f16x2(v.x, v.y);
        *(uint32_t*)&woh[4 * (size_t)j + 2] = pack_f16x2(v.z, v.w);
    }
}

// ---------------- fp16 GEMM: C = A @ B^T (+bias), single fp16 both sides --
// 128x256 CTA tile, 8 warps 2x4, warp tile 64x64, KC=64 double-buffered.
// mode 0: fp32 C + bias.  mode 1: QKV epilogue -> q fp16 hi/lo (pre-scaled),
// k/v single fp16, per-(b,h) layout.
#define QSCALE 0.18033688011112042f
#define KC     64
#define ROWB   144
#define OFF_B  (128 * ROWB)                  // 18432
#define STAGE_B (OFF_B + 256 * ROWB)         // 55296
#define GEMM_SMEM (2 * STAGE_B)              // 110592

__global__ __launch_bounds__(256, 1) void mma_gemm(
    const __half* __restrict__ A, const __half* __restrict__ B,
    const float* __restrict__ bias, float* __restrict__ C,
    __half* __restrict__ qh, __half* __restrict__ ql,
    __half* __restrict__ kf, __half* __restrict__ vf,
    int Nn, int K, int mode)
{
    extern __shared__ char smem[];
    const uint32_t sb = smem_u32(smem);
    const int tid  = threadIdx.x;
    const int wid  = tid >> 5;
    const int lane = tid & 31;
    const int wm = wid >> 2;
    const int wn = wid & 3;

    const size_t rowBase = (size_t)blockIdx.y * 128;
    const size_t colBase = (size_t)blockIdx.x * 256;

    const __half* sA = A + rowBase * K;
    const __half* sB = B + colBase * K;

    const int r0l = tid >> 3;
    const int lj  = tid & 7;
    auto load_chunk = [&](int c, int stage) {
        const uint32_t st = sb + stage * STAGE_B;
        const int kof = c * KC + lj * 8;
        #pragma unroll
        for (int it = 0; it < 12; it++) {
            const int r = it * 32 + r0l;           // 0..383
            uint32_t dst; const __half* src;
            if (it < 4) { dst = st + r * ROWB + lj * 16;
                          src = sA + (size_t)r * K + kof; }
            else        { const int rr = r - 128;
                          dst = st + OFF_B + rr * ROWB + lj * 16;
                          src = sB + (size_t)rr * K + kof; }
            cp_async16(dst, src);
        }
        CP_COMMIT();
    };

    float acc[4][8][4];
    #pragma unroll
    for (int i = 0; i < 4; i++)
        #pragma unroll
        for (int j = 0; j < 8; j++)
            #pragma unroll
            for (int k = 0; k < 4; k++) acc[i][j][k] = 0.f;

    const int arow = ((lane >> 3) & 1) * 8 + (lane & 7);
    const int acol = ((lane >> 4) & 1) * 8;
    const int brow = ((lane >> 4) & 1) * 8 + (lane & 7);
    const int bcol = ((lane >> 3) & 1) * 8;

    const int nch = K / KC;
    load_chunk(0, 0);

    for (int c = 0; c < nch; c++) {
        const int s = c & 1;
        if (c + 1 < nch) { load_chunk(c + 1, s ^ 1); CP_WAIT(1); }
        else             { CP_WAIT(0); }
        __syncthreads();

        const uint32_t stS = sb + s * STAGE_B;

        #pragma unroll
        for (int kk = 0; kk < 4; kk++) {
            const int k0 = kk * 16;
            uint32_t af[4][4];
            #pragma unroll
            for (int mt = 0; mt < 4; mt++) {
                const uint32_t ra = stS + (wm * 64 + mt * 16 + arow) * ROWB
                                        + (k0 + acol) * 2;
                LDSM4(af[mt], ra);
            }
            uint32_t bf[8][2];
            #pragma unroll
            for (int np = 0; np < 4; np++) {
                const uint32_t rb = stS + OFF_B
                    + (wn * 64 + np * 16 + brow) * ROWB + (k0 + bcol) * 2;
                uint32_t r[4];
                LDSM4(r, rb);
                bf[2 * np][0]     = r[0]; bf[2 * np][1]     = r[1];
                bf[2 * np + 1][0] = r[2]; bf[2 * np + 1][1] = r[3];
            }
            #pragma unroll
            for (int mt = 0; mt < 4; mt++)
                #pragma unroll
                for (int nt = 0; nt < 8; nt++)
                    mma_f16(acc[mt][nt], af[mt], bf[nt]);
        }
        __syncthreads();
    }

    // ---- epilogue ----
    const int g  = lane >> 2;
    const int t4 = lane & 3;
    if (mode == 0) {
        #pragma unroll
        for (int mt = 0; mt < 4; mt++) {
            const size_t r0 = rowBase + wm * 64 + mt * 16 + g;
            #pragma unroll
            for (int nt = 0; nt < 8; nt++) {
                const size_t cc = colBase + wn * 64 + nt * 8 + t4 * 2;
                const float b0 = bias[cc], b1 = bias[cc + 1];
                float2 v0, v1;
                v0.x = acc[mt][nt][0] + b0; v0.y = acc[mt][nt][1] + b1;
                v1.x = acc[mt][nt][2] + b0; v1.y = acc[mt][nt][3] + b1;
                *(float2*)&C[r0 * Nn + cc]       = v0;
                *(float2*)&C[(r0 + 8) * Nn + cc] = v1;
            }
        }
    } else {
        #pragma unroll
        for (int mt = 0; mt < 4; mt++) {
            const int tok0 = (int)rowBase + wm * 64 + mt * 16 + g;
            #pragma unroll
            for (int nt = 0; nt < 8; nt++) {
                const int cc = (int)colBase + wn * 64 + nt * 8 + t4 * 2;
                const int sec = cc >> 10;            // 0=q 1=k 2=v
                const int rest = cc & 1023;
                const int h = rest >> 6, d = rest & 63;
                float v00 = acc[mt][nt][0] + bias[cc];
                float v01 = acc[mt][nt][1] + bias[cc + 1];
                float v10 = acc[mt][nt][2] + bias[cc];
                float v11 = acc[mt][nt][3] + bias[cc + 1];
                const size_t o0 = (((size_t)((tok0 >> 11) * NH + h)) * SEQ
                                   + (tok0 & 2047)) * HD + d;
                const size_t o1 = o0 + 8 * HD;
                if (sec == 0) {
                    v00 *= QSCALE; v01 *= QSCALE; v10 *= QSCALE; v11 *= QSCALE;
                    float h00 = f16rt(v00), h01 = f16rt(v01);
                    float h10 = f16rt(v10), h11 = f16rt(v11);
                    *(uint32_t*)&qh[o0] = pack_f16x2(h00, h01);
                    *(uint32_t*)&ql[o0] = pack_f16x2(v00 - h00, v01 - h01);
                    *(uint32_t*)&qh[o1] = pack_f16x2(h10, h11);
                    *(uint32_t*)&ql[o1] = pack_f16x2(v10 - h10, v11 - h11);
                } else {
                    __half* p = (sec == 1) ? kf : vf;
                    *(uint32_t*)&p[o0] = pack_f16x2(v00, v01);
                    *(uint32_t*)&p[o1] = pack_f16x2(v10, v11);
                }
            }
        }
    }
}

// ---------------- fp16 flash attention (round-12, validated) --------------
// QK^T = Qh*K + Ql*K (Q split, K single).  PV = P*V (single/single).
// Epilogue writes single fp16 attention output.
#define ATILE  (128 * ROWB)          // 18432
#define ASTAGE (2 * ATILE)           // K, V single
#define MHA_SMEM (2 * ATILE + 2 * ASTAGE)   // 110592 B

__global__ __launch_bounds__(256, 1) void mha_mma(
    const __half* __restrict__ qh, const __half* __restrict__ ql,
    const __half* __restrict__ kf, const __half* __restrict__ vf,
    __half* __restrict__ af)
{
    extern __shared__ char smem[];
    const uint32_t sb = smem_u32(smem);
    const int tid  = threadIdx.x;
    const int wid  = tid >> 5;
    const int lane = tid & 31;

    const int qtile = blockIdx.x;
    const int bh    = blockIdx.y;
    const size_t base = (size_t)bh * SEQ * HD;

    const int lr = tid >> 3;
    const int lj = tid & 7;

    // Q hi/lo tiles
    {
        const __half* qsrc[2] = { qh + base, ql + base };
        #pragma unroll
        for (int it = 0; it < 8; it++) {
            const int t = it >> 2;
            const int r = lr + (it & 3) * 32;
            const uint32_t dst = sb + t * ATILE + r * ROWB + lj * 16;
            cp_async16(dst, qsrc[t] + (size_t)(qtile * 128 + r) * HD + lj * 8);
        }
        CP_COMMIT();
    }

    const __half* kvsrc[2] = { kf + base, vf + base };
    auto load_kv = [&](int kb, int stage) {
        const uint32_t st = sb + 2 * ATILE + stage * ASTAGE;
        #pragma unroll
        for (int it = 0; it < 8; it++) {
            const int t = it >> 2;
            const int r = lr + (it & 3) * 32;
            const uint32_t dst = st + t * ATILE + r * ROWB + lj * 16;
            cp_async16(dst, kvsrc[t] + (size_t)(kb * 128 + r) * HD + lj * 8);
        }
        CP_COMMIT();
    };
    load_kv(0, 0);

    const int arow = ((lane >> 3) & 1) * 8 + (lane & 7);
    const int acol = ((lane >> 4) & 1) * 8;
    const int brow = ((lane >> 4) & 1) * 8 + (lane & 7);
    const int bcol = ((lane >> 3) & 1) * 8;
    const int vrow = ((lane >> 3) & 1) * 8 + (lane & 7);
    const int vcol = ((lane >> 4) & 1) * 8;

    CP_WAIT(1);
    __syncthreads();

    uint32_t qfh[4][4], qfl[4][4];
    #pragma unroll
    for (int kk = 0; kk < 4; kk++) {
        const uint32_t ra = sb + (wid * 16 + arow) * ROWB + (kk * 16 + acol) * 2;
        LDSM4(qfh[kk], ra);
        LDSM4(qfl[kk], ra + ATILE);
    }

    float oacc[8][4];
    #pragma unroll
    for (int i = 0; i < 8; i++)
        #pragma unroll
        for (int j = 0; j < 4; j++) oacc[i][j] = 0.f;
    float m0 = -1e30f, m1 = -1e30f, l0 = 0.f, l1 = 0.f;

    for (int kb = 0; kb < SEQ / 128; kb++) {
        const int s = kb & 1;
        if (kb + 1 < SEQ / 128) { load_kv(kb + 1, s ^ 1); CP_WAIT(1); }
        else                    { CP_WAIT(0); }
        __syncthreads();

        const uint32_t stK = sb + 2 * ATILE + s * ASTAGE;
        const uint32_t stV = stK + ATILE;

        // ---- S = (Qh + Ql) K^T ----
        float sacc[16][4];
        #pragma unroll
        for (int t = 0; t < 16; t++)
            #pragma unroll
            for (int j = 0; j < 4; j++) sacc[t][j] = 0.f;

        #pragma unroll
        for (int np = 0; np < 8; np++) {
            #pragma unroll
            for (int kk = 0; kk < 4; kk++) {
                const uint32_t rK = stK + (np * 16 + brow) * ROWB
                                        + (kk * 16 + bcol) * 2;
                uint32_t rk[4];
                LDSM4(rk, rK);
                mma_f16(sacc[2 * np],     qfh[kk], &rk[0]);
                mma_f16(sacc[2 * np],     qfl[kk], &rk[0]);
                mma_f16(sacc[2 * np + 1], qfh[kk], &rk[2]);
                mma_f16(sacc[2 * np + 1], qfl[kk], &rk[2]);
            }
        }

        // ---- online softmax (base-2) ----
        float tm0 = -1e30f, tm1 = -1e30f;
        #pragma unroll
        for (int t = 0; t < 16; t++) {
            tm0 = fmaxf(tm0, fmaxf(sacc[t][0], sacc[t][1]));
            tm1 = fmaxf(tm1, fmaxf(sacc[t][2], sacc[t][3]));
        }
        tm0 = fmaxf(tm0, __shfl_xor_sync(0xFFFFFFFFu, tm0, 1));
        tm0 = fmaxf(tm0, __shfl_xor_sync(0xFFFFFFFFu, tm0, 2));
        tm1 = fmaxf(tm1, __shfl_xor_sync(0xFFFFFFFFu, tm1, 1));
        tm1 = fmaxf(tm1, __shfl_xor_sync(0xFFFFFFFFu, tm1, 2));

        const float nm0 = fmaxf(m0, tm0);
        const float nm1 = fmaxf(m1, tm1);
        const float a0 = ex2f(m0 - nm0);
        const float a1 = ex2f(m1 - nm1);
        m0 = nm0; m1 = nm1;

        float rs0 = 0.f, rs1 = 0.f;
        #pragma unroll
        for (int t = 0; t < 16; t++) {
            sacc[t][0] = ex2f(sacc[t][0] - nm0);
            sacc[t][1] = ex2f(sacc[t][1] - nm0);
            sacc[t][2] = ex2f(sacc[t][2] - nm1);
            sacc[t][3] = ex2f(sacc[t][3] - nm1);
            rs0 += sacc[t][0] + sacc[t][1];
            rs1 += sacc[t][2] + sacc[t][3];
        }
        rs0 += __shfl_xor_sync(0xFFFFFFFFu, rs0, 1);
        rs0 += __shfl_xor_sync(0xFFFFFFFFu, rs0, 2);
        rs1 += __shfl_xor_sync(0xFFFFFFFFu, rs1, 1);
        rs1 += __shfl_xor_sync(0xFFFFFFFFu, rs1, 2);
        l0 = l0 * a0 + rs0;
        l1 = l1 * a1 + rs1;

        #pragma unroll
        for (int nt = 0; nt < 8; nt++) {
            oacc[nt][0] *= a0; oacc[nt][1] *= a0;
            oacc[nt][2] *= a1; oacc[nt][3] *= a1;
        }

        // ---- O += P V (single fp16 P and V) ----
        #pragma unroll
        for (int kc = 0; kc < 8; kc++) {
            const int t0 = 2 * kc, t1 = 2 * kc + 1;
            uint32_t pa[4];
            pa[0] = pack_f16x2(sacc[t0][0], sacc[t0][1]);
            pa[1] = pack_f16x2(sacc[t0][2], sacc[t0][3]);
            pa[2] = pack_f16x2(sacc[t1][0], sacc[t1][1]);
            pa[3] = pack_f16x2(sacc[t1][2], sacc[t1][3]);
            #pragma unroll
            for (int nv = 0; nv < 4; nv++) {
                const uint32_t rV = stV + (kc * 16 + vrow) * ROWB
                                        + (nv * 16 + vcol) * 2;
                uint32_t vv[4];
                LDSM4T(vv, rV);
                mma_f16(oacc[2 * nv],     pa, &vv[0]);
                mma_f16(oacc[2 * nv + 1], pa, &vv[2]);
            }
        }
        __syncthreads();
    }

    // ---- epilogue: normalize, write single fp16 to g_af ----
    const int g  = lane >> 2;
    const int t4 = lane & 3;
    const float inv0 = 1.f / l0;
    const float inv1 = 1.f / l1;
    const int b = bh >> 4, h = bh & 15;
    const size_t tok0 = (size_t)b * SEQ + qtile * 128 + wid * 16 + g;
    const int colb = h * HD;
    #pragma unroll
    for (int nt = 0; nt < 8; nt++) {
        const int cc = colb + nt * 8 + 2 * t4;
        *(uint32_t*)&af[tok0 * EMB + cc] =
            pack_f16x2(oacc[nt][0] * inv0, oacc[nt][1] * inv0);
        *(uint32_t*)&af[(tok0 + 8) * EMB + cc] =
            pack_f16x2(oacc[nt][2] * inv1, oacc[nt][3] * inv1);
    }
}

// ---------------------------------------------------------------------------
extern "C" void kernel_launch(void* const* d_in, const int* in_sizes, int n_in,
                              void* d_out, int out_size)
{
    const float* x     = (const float*)d_in[0];
    const float* w_in  = (const float*)d_in[1];
    const float* b_in  = (const float*)d_in[2];
    const float* w_out = (const float*)d_in[3];
    const float* b_out = (const float*)d_in[4];
    float* out = (float*)d_out;

    __half *xh, *wih, *woh, *af, *qh, *ql, *kf, *vf;
    cudaGetSymbolAddress((void**)&xh,  g_xh);
    cudaGetSymbolAddress((void**)&wih, g_wih);
    cudaGetSymbolAddress((void**)&woh, g_woh);
    cudaGetSymbolAddress((void**)&af,  g_af);
    cudaGetSymbolAddress((void**)&qh,  g_qh);
    cudaGetSymbolAddress((void**)&ql,  g_ql);
    cudaGetSymbolAddress((void**)&kf,  g_kf);
    cudaGetSymbolAddress((void**)&vf,  g_vf);

    cudaFuncSetAttribute(mma_gemm,
                         cudaFuncAttributeMaxDynamicSharedMemorySize, GEMM_SMEM);
    cudaFuncSetAttribute(mha_mma,
                         cudaFuncAttributeMaxDynamicSharedMemorySize, MHA_SMEM);

    // 0) fp32 -> fp16 conversions in one launch
    prep<<<(NPREP + 255) / 256, 256>>>(x, w_in, w_out, xh, wih, woh);

    // 1) QKV projection (fp16 single x single), fused epilogue
    mma_gemm<<<dim3(E3 / 256, TOK / 128), 256, GEMM_SMEM>>>(
        xh, wih, b_in, nullptr, qh, ql, kf, vf, E3, EMB, 1);

    // 2) fp16 flash attention -> single fp16 af
    mha_mma<<<dim3(SEQ / 128, 2 * NH), 256, MHA_SMEM>>>(
        qh, ql, kf, vf, af);

    // 3) out-projection (fp16 single x single), fp32 out + bias
    mma_gemm<<<dim3(EMB / 256, TOK / 128), 256, GEMM_SMEM>>>(
        af, woh, b_out, out,
        nullptr, nullptr, nullptr, nullptr, EMB, EMB, 0);
}